// round 1
// baseline (speedup 1.0000x reference)
#include <cuda_runtime.h>
#include <cuda_bf16.h>
#include <cstdint>
#include <cstddef>

// Problem constants
#define BATCH 2
#define SEQ   2048
#define DIM   1024
#define HEADS 16
#define HSZ   64
#define ROWS  (BATCH*SEQ)          // 4096
#define FFDIM (4*DIM)              // 4096

// ---------------- scratch (static device arrays; no allocations) -------------
__device__ float g_h  [ROWS * DIM];     // LN output (reused for ln1 and ln2)
__device__ float g_q  [ROWS * DIM];
__device__ float g_k  [ROWS * DIM];
__device__ float g_v  [ROWS * DIM];
__device__ float g_att[ROWS * DIM];
__device__ float g_x1 [ROWS * DIM];     // x + attn_out
__device__ float g_ff [ROWS * FFDIM];   // relu(h2@W1+b1)

// ============================ LayerNorm ======================================
__global__ __launch_bounds__(256)
void ln_kernel(const float* __restrict__ x, const float* __restrict__ g,
               const float* __restrict__ b, float* __restrict__ y)
{
    const int row = blockIdx.x;
    const int tid = threadIdx.x;
    const float* xr = x + (size_t)row * DIM;

    float4 v = *(const float4*)(xr + tid * 4);
    float s  = v.x + v.y + v.z + v.w;
    float ss = v.x*v.x + v.y*v.y + v.z*v.z + v.w*v.w;
    #pragma unroll
    for (int off = 16; off >= 1; off >>= 1) {
        s  += __shfl_xor_sync(0xffffffffu, s,  off);
        ss += __shfl_xor_sync(0xffffffffu, ss, off);
    }
    __shared__ float sbuf[8], ssbuf[8];
    const int w = tid >> 5, l = tid & 31;
    if (l == 0) { sbuf[w] = s; ssbuf[w] = ss; }
    __syncthreads();
    float st = 0.f, sst = 0.f;
    #pragma unroll
    for (int i = 0; i < 8; i++) { st += sbuf[i]; sst += ssbuf[i]; }
    const float mean = st * (1.0f / DIM);
    const float var  = sst * (1.0f / DIM) - mean * mean;
    const float rstd = rsqrtf(var + 1e-5f);

    float4 gg = *(const float4*)(g + tid * 4);
    float4 bb = *(const float4*)(b + tid * 4);
    float4 o;
    o.x = (v.x - mean) * rstd * gg.x + bb.x;
    o.y = (v.y - mean) * rstd * gg.y + bb.y;
    o.z = (v.z - mean) * rstd * gg.z + bb.z;
    o.w = (v.w - mean) * rstd * gg.w + bb.w;
    *(float4*)(y + (size_t)row * DIM + tid * 4) = o;
}

// ============================ SGEMM 128x128x8 ================================
// WMODE: 0 = W is row-major [K,N]; 1 = QKV layout W[h,d,k]=(n>>6)*D*64 + d*64 + (n&63)
// EPI:   0 = C=acc; 1 = C=relu(acc+bias); 2 = C=acc+bias+res
template<int WMODE>
__device__ __forceinline__ float4 load_w(const float* __restrict__ W, int k, int n, int N)
{
    if (WMODE == 0) return *(const float4*)(W + (size_t)k * N + n);
    else            return *(const float4*)(W + (size_t)(n >> 6) * (DIM * HSZ) + k * HSZ + (n & 63));
}

template<int WMODE, int EPI>
__global__ __launch_bounds__(256)
void sgemm_kernel(const float* __restrict__ A, const float* __restrict__ W,
                  const float* __restrict__ bias, const float* __restrict__ res,
                  float* __restrict__ C, int M, int N, int K)
{
    __shared__ float As[8 * 128];
    __shared__ float Bs[8 * 128];

    const int tid = threadIdx.x;
    const int tx = tid & 15;
    const int ty = tid >> 4;
    const int m0 = blockIdx.y * 128;
    const int n0 = blockIdx.x * 128;

    const int a_row = tid >> 1;           // 0..127
    const int a_col = (tid & 1) * 4;      // 0 or 4
    const int b_row = tid >> 5;           // 0..7
    const int b_col = (tid & 31) * 4;     // 0..124

    const float* Aptr = A + (size_t)(m0 + a_row) * K + a_col;

    float acc[8][8];
    #pragma unroll
    for (int i = 0; i < 8; i++)
        #pragma unroll
        for (int j = 0; j < 8; j++) acc[i][j] = 0.f;

    float4 a_reg = *(const float4*)(Aptr);
    float4 b_reg = load_w<WMODE>(W, b_row, n0 + b_col, N);

    for (int k0 = 0; k0 < K; k0 += 8) {
        As[(a_col + 0) * 128 + a_row] = a_reg.x;
        As[(a_col + 1) * 128 + a_row] = a_reg.y;
        As[(a_col + 2) * 128 + a_row] = a_reg.z;
        As[(a_col + 3) * 128 + a_row] = a_reg.w;
        *(float4*)&Bs[b_row * 128 + b_col] = b_reg;
        __syncthreads();

        if (k0 + 8 < K) {
            a_reg = *(const float4*)(Aptr + k0 + 8);
            b_reg = load_w<WMODE>(W, k0 + 8 + b_row, n0 + b_col, N);
        }

        #pragma unroll
        for (int kk = 0; kk < 8; kk++) {
            float4 a0 = *(const float4*)&As[kk * 128 + ty * 4];
            float4 a1 = *(const float4*)&As[kk * 128 + 64 + ty * 4];
            float4 b0 = *(const float4*)&Bs[kk * 128 + tx * 4];
            float4 b1 = *(const float4*)&Bs[kk * 128 + 64 + tx * 4];
            float af[8] = {a0.x, a0.y, a0.z, a0.w, a1.x, a1.y, a1.z, a1.w};
            float bf[8] = {b0.x, b0.y, b0.z, b0.w, b1.x, b1.y, b1.z, b1.w};
            #pragma unroll
            for (int i = 0; i < 8; i++)
                #pragma unroll
                for (int j = 0; j < 8; j++)
                    acc[i][j] = fmaf(af[i], bf[j], acc[i][j]);
        }
        __syncthreads();
    }

    // epilogue
    #pragma unroll
    for (int ih = 0; ih < 2; ih++) {
        #pragma unroll
        for (int i = 0; i < 4; i++) {
            const int r = m0 + ih * 64 + ty * 4 + i;
            #pragma unroll
            for (int jh = 0; jh < 2; jh++) {
                const int c = n0 + jh * 64 + tx * 4;
                float4 v;
                v.x = acc[ih * 4 + i][jh * 4 + 0];
                v.y = acc[ih * 4 + i][jh * 4 + 1];
                v.z = acc[ih * 4 + i][jh * 4 + 2];
                v.w = acc[ih * 4 + i][jh * 4 + 3];
                if (EPI == 1 || EPI == 2) {
                    float4 bb = *(const float4*)(bias + c);
                    v.x += bb.x; v.y += bb.y; v.z += bb.z; v.w += bb.w;
                }
                if (EPI == 1) {
                    v.x = fmaxf(v.x, 0.f); v.y = fmaxf(v.y, 0.f);
                    v.z = fmaxf(v.z, 0.f); v.w = fmaxf(v.w, 0.f);
                }
                if (EPI == 2) {
                    float4 rr = *(const float4*)(res + (size_t)r * N + c);
                    v.x += rr.x; v.y += rr.y; v.z += rr.z; v.w += rr.w;
                }
                *(float4*)(C + (size_t)r * N + c) = v;
            }
        }
    }
}

// ============================ Flash attention ================================
// grid: (SEQ/64, HEADS, BATCH), block 256. Q/K/V in [B,T,H*HS] layout.
// Per block: 64 queries x full key loop with online softmax. fp32 throughout.
#define ATTN_SMEM_FLOATS (3 * 64 * 64 + 64 * 68)
#define ATTN_SMEM_BYTES  (ATTN_SMEM_FLOATS * 4)

__global__ __launch_bounds__(256)
void attn_kernel(const float* __restrict__ Q, const float* __restrict__ Kp,
                 const float* __restrict__ V, float* __restrict__ O)
{
    extern __shared__ float sm[];
    float* Qs = sm;                  // [k][r]  64x64
    float* Ks = sm + 4096;           // [k][c]  64x64
    float* Vs = sm + 8192;           // [kk][j] 64x64
    float* Ps = sm + 12288;          // [kk][r] 64x68 (padded)

    const int tid = threadIdx.x;
    const int tx = tid & 15;
    const int ty = tid >> 4;
    const int qb = blockIdx.x * 64;
    const int h  = blockIdx.y;
    const int b  = blockIdx.z;

    const size_t baseQ = ((size_t)(b * SEQ + qb)) * DIM + h * HSZ;

    // load Q tile transposed: Qs[k*64 + r]
    #pragma unroll
    for (int it = 0; it < 4; it++) {
        int i = tid + it * 256;
        int r = i >> 4;
        int k4 = (i & 15) << 2;
        float4 qv = *(const float4*)(Q + baseQ + (size_t)r * DIM + k4);
        Qs[(k4 + 0) * 64 + r] = qv.x;
        Qs[(k4 + 1) * 64 + r] = qv.y;
        Qs[(k4 + 2) * 64 + r] = qv.z;
        Qs[(k4 + 3) * 64 + r] = qv.w;
    }

    float m_run[4], l_run[4], acc[4][4];
    #pragma unroll
    for (int i = 0; i < 4; i++) {
        m_run[i] = -1e30f; l_run[i] = 0.f;
        #pragma unroll
        for (int j = 0; j < 4; j++) acc[i][j] = 0.f;
    }

    for (int kc = 0; kc < SEQ; kc += 64) {
        __syncthreads();   // previous PV done with Ps/Vs
        const size_t baseK = ((size_t)(b * SEQ + kc)) * DIM + h * HSZ;
        #pragma unroll
        for (int it = 0; it < 4; it++) {
            int i = tid + it * 256;
            int r = i >> 4;
            int k4 = (i & 15) << 2;
            float4 kv = *(const float4*)(Kp + baseK + (size_t)r * DIM + k4);
            Ks[(k4 + 0) * 64 + r] = kv.x;
            Ks[(k4 + 1) * 64 + r] = kv.y;
            Ks[(k4 + 2) * 64 + r] = kv.z;
            Ks[(k4 + 3) * 64 + r] = kv.w;
            float4 vv = *(const float4*)(V + baseK + (size_t)r * DIM + k4);
            *(float4*)&Vs[r * 64 + k4] = vv;
        }
        __syncthreads();

        // S = Q K^T * scale  (4x4 per thread)
        float s4[4][4];
        #pragma unroll
        for (int i = 0; i < 4; i++)
            #pragma unroll
            for (int j = 0; j < 4; j++) s4[i][j] = 0.f;
        #pragma unroll 8
        for (int k = 0; k < 64; k++) {
            float4 qa = *(const float4*)&Qs[k * 64 + ty * 4];
            float4 kb = *(const float4*)&Ks[k * 64 + tx * 4];
            float aq[4] = {qa.x, qa.y, qa.z, qa.w};
            float bk[4] = {kb.x, kb.y, kb.z, kb.w};
            #pragma unroll
            for (int i = 0; i < 4; i++)
                #pragma unroll
                for (int j = 0; j < 4; j++)
                    s4[i][j] = fmaf(aq[i], bk[j], s4[i][j]);
        }
        #pragma unroll
        for (int i = 0; i < 4; i++)
            #pragma unroll
            for (int j = 0; j < 4; j++) s4[i][j] *= 0.125f;  // 1/sqrt(64)

        // online softmax: row max across tx group (16 lanes)
        float mloc[4];
        #pragma unroll
        for (int i = 0; i < 4; i++)
            mloc[i] = fmaxf(fmaxf(s4[i][0], s4[i][1]), fmaxf(s4[i][2], s4[i][3]));
        #pragma unroll
        for (int off = 8; off >= 1; off >>= 1)
            #pragma unroll
            for (int i = 0; i < 4; i++)
                mloc[i] = fmaxf(mloc[i], __shfl_xor_sync(0xffffffffu, mloc[i], off));

        float alpha[4], mnew[4], lloc[4];
        #pragma unroll
        for (int i = 0; i < 4; i++) {
            mnew[i]  = fmaxf(m_run[i], mloc[i]);
            alpha[i] = __expf(m_run[i] - mnew[i]);
            m_run[i] = mnew[i];
            lloc[i]  = 0.f;
        }

        float p[4][4];
        #pragma unroll
        for (int i = 0; i < 4; i++)
            #pragma unroll
            for (int j = 0; j < 4; j++) {
                p[i][j] = __expf(s4[i][j] - mnew[i]);
                lloc[i] += p[i][j];
            }
        #pragma unroll
        for (int off = 8; off >= 1; off >>= 1)
            #pragma unroll
            for (int i = 0; i < 4; i++)
                lloc[i] += __shfl_xor_sync(0xffffffffu, lloc[i], off);
        #pragma unroll
        for (int i = 0; i < 4; i++) {
            l_run[i] = l_run[i] * alpha[i] + lloc[i];
            #pragma unroll
            for (int j = 0; j < 4; j++) acc[i][j] *= alpha[i];
        }

        // write P transposed: Ps[kk*68 + r]
        #pragma unroll
        for (int j = 0; j < 4; j++) {
            float4 pv = make_float4(p[0][j], p[1][j], p[2][j], p[3][j]);
            *(float4*)&Ps[(tx * 4 + j) * 68 + ty * 4] = pv;
        }
        __syncthreads();

        // O += P @ V
        #pragma unroll 8
        for (int kk = 0; kk < 64; kk++) {
            float4 pa = *(const float4*)&Ps[kk * 68 + ty * 4];
            float4 vb = *(const float4*)&Vs[kk * 64 + tx * 4];
            float ap[4] = {pa.x, pa.y, pa.z, pa.w};
            float bv[4] = {vb.x, vb.y, vb.z, vb.w};
            #pragma unroll
            for (int i = 0; i < 4; i++)
                #pragma unroll
                for (int j = 0; j < 4; j++)
                    acc[i][j] = fmaf(ap[i], bv[j], acc[i][j]);
        }
    }

    // normalize + store
    #pragma unroll
    for (int i = 0; i < 4; i++) {
        const float rl = 1.0f / l_run[i];
        float4 o = make_float4(acc[i][0] * rl, acc[i][1] * rl, acc[i][2] * rl, acc[i][3] * rl);
        *(float4*)(O + baseQ + (size_t)(ty * 4 + i) * DIM + tx * 4) = o;
    }
}

// ============================ launch =========================================
extern "C" void kernel_launch(void* const* d_in, const int* in_sizes, int n_in,
                              void* d_out, int out_size)
{
    const float* x     = (const float*)d_in[0];
    const float* Wq    = (const float*)d_in[1];
    const float* Wk    = (const float*)d_in[2];
    const float* Wv    = (const float*)d_in[3];
    const float* Wo    = (const float*)d_in[4];
    const float* bo    = (const float*)d_in[5];
    const float* W1    = (const float*)d_in[6];
    const float* b1    = (const float*)d_in[7];
    const float* W2    = (const float*)d_in[8];
    const float* b2    = (const float*)d_in[9];
    const float* ln1_g = (const float*)d_in[10];
    const float* ln1_b = (const float*)d_in[11];
    const float* ln2_g = (const float*)d_in[12];
    const float* ln2_b = (const float*)d_in[13];
    float* out = (float*)d_out;

    float *ph, *pq, *pk, *pv, *patt, *px1, *pff;
    cudaGetSymbolAddress((void**)&ph,   g_h);
    cudaGetSymbolAddress((void**)&pq,   g_q);
    cudaGetSymbolAddress((void**)&pk,   g_k);
    cudaGetSymbolAddress((void**)&pv,   g_v);
    cudaGetSymbolAddress((void**)&patt, g_att);
    cudaGetSymbolAddress((void**)&px1,  g_x1);
    cudaGetSymbolAddress((void**)&pff,  g_ff);

    cudaFuncSetAttribute(attn_kernel, cudaFuncAttributeMaxDynamicSharedMemorySize,
                         ATTN_SMEM_BYTES);

    // 1) h = LN1(x)
    ln_kernel<<<ROWS, 256>>>(x, ln1_g, ln1_b, ph);

    // 2) Q,K,V projections (QKV weight layout, no bias)
    dim3 gProj(DIM / 128, ROWS / 128);   // (8,32)
    sgemm_kernel<1, 0><<<gProj, 256>>>(ph, Wq, nullptr, nullptr, pq, ROWS, DIM, DIM);
    sgemm_kernel<1, 0><<<gProj, 256>>>(ph, Wk, nullptr, nullptr, pk, ROWS, DIM, DIM);
    sgemm_kernel<1, 0><<<gProj, 256>>>(ph, Wv, nullptr, nullptr, pv, ROWS, DIM, DIM);

    // 3) attention (fused softmax)
    dim3 gAttn(SEQ / 64, HEADS, BATCH);  // (32,16,2)
    attn_kernel<<<gAttn, 256, ATTN_SMEM_BYTES>>>(pq, pk, pv, patt);

    // 4) x1 = x + attn@Wo + bo
    sgemm_kernel<0, 2><<<gProj, 256>>>(patt, Wo, bo, x, px1, ROWS, DIM, DIM);

    // 5) h2 = LN2(x1)
    ln_kernel<<<ROWS, 256>>>(px1, ln2_g, ln2_b, ph);

    // 6) ff = relu(h2 @ W1 + b1)
    dim3 gFF1(FFDIM / 128, ROWS / 128);  // (32,32)
    sgemm_kernel<0, 1><<<gFF1, 256>>>(ph, W1, b1, nullptr, pff, ROWS, FFDIM, DIM);

    // 7) out = x1 + ff @ W2 + b2
    sgemm_kernel<0, 2><<<gProj, 256>>>(pff, W2, b2, px1, out, ROWS, DIM, FFDIM);
}

// round 3
// speedup vs baseline: 1.4638x; 1.4638x over previous
#include <cuda_runtime.h>
#include <cuda_bf16.h>
#include <cstdint>
#include <cstddef>

// Problem constants
#define BATCH 2
#define SEQ   2048
#define DIM   1024
#define HEADS 16
#define HSZ   64
#define ROWS  (BATCH*SEQ)          // 4096
#define FFDIM (4*DIM)              // 4096

// ======================= PTX helpers (family-safe only) ======================
__device__ __forceinline__ uint32_t smem_to_u32(const void* smem_ptr) {
    uint32_t addr;
    asm("{ .reg .u64 tmp; cvta.to.shared.u64 tmp, %1; cvt.u32.u64 %0, tmp; }"
        : "=r"(addr) : "l"(smem_ptr));
    return addr;
}

__device__ __forceinline__ void cp16(uint32_t saddr, const void* gptr) {
    asm volatile("cp.async.cg.shared.global [%0], [%1], 16;"
                 :: "r"(saddr), "l"(gptr) : "memory");
}
__device__ __forceinline__ void cp_commit() {
    asm volatile("cp.async.commit_group;" ::: "memory");
}
__device__ __forceinline__ void cp_wait1() {
    asm volatile("cp.async.wait_group 1;" ::: "memory");
}
__device__ __forceinline__ void cp_wait0() {
    asm volatile("cp.async.wait_group 0;" ::: "memory");
}

__device__ __forceinline__ void ldsm4(uint32_t addr, uint32_t* r) {
    asm volatile("ldmatrix.sync.aligned.m8n8.x4.shared.b16 {%0,%1,%2,%3}, [%4];"
                 : "=r"(r[0]), "=r"(r[1]), "=r"(r[2]), "=r"(r[3]) : "r"(addr));
}

__device__ __forceinline__ void mma16816(float* c, const uint32_t* a, const uint32_t* b) {
    asm volatile(
        "mma.sync.aligned.m16n8k16.row.col.f32.bf16.bf16.f32 "
        "{%0,%1,%2,%3}, {%4,%5,%6,%7}, {%8,%9}, {%0,%1,%2,%3};"
        : "+f"(c[0]), "+f"(c[1]), "+f"(c[2]), "+f"(c[3])
        : "r"(a[0]), "r"(a[1]), "r"(a[2]), "r"(a[3]), "r"(b[0]), "r"(b[1]));
}

// ---------------- scratch (static device arrays; no allocations) -------------
__device__ float g_q  [ROWS * DIM];
__device__ float g_k  [ROWS * DIM];
__device__ float g_v  [ROWS * DIM];
__device__ float g_x1 [ROWS * DIM];     // x + attn_out (fp32)

__device__ __nv_bfloat16 g_hh [ROWS * DIM];     // LN output hi (ln1 / ln2 reuse)
__device__ __nv_bfloat16 g_hl [ROWS * DIM];     // LN output lo
__device__ __nv_bfloat16 g_atth[ROWS * DIM];
__device__ __nv_bfloat16 g_attl[ROWS * DIM];
__device__ __nv_bfloat16 g_ffh [ROWS * FFDIM];
__device__ __nv_bfloat16 g_ffl [ROWS * FFDIM];

// weights, transposed to [N, K] K-major, hi/lo split
__device__ __nv_bfloat16 g_wqh[DIM * DIM],   g_wql[DIM * DIM];
__device__ __nv_bfloat16 g_wkh[DIM * DIM],   g_wkl[DIM * DIM];
__device__ __nv_bfloat16 g_wvh[DIM * DIM],   g_wvl[DIM * DIM];
__device__ __nv_bfloat16 g_woh[DIM * DIM],   g_wol[DIM * DIM];
__device__ __nv_bfloat16 g_w1h[FFDIM * DIM], g_w1l[FFDIM * DIM];
__device__ __nv_bfloat16 g_w2h[DIM * FFDIM], g_w2l[DIM * FFDIM];

// ==================== weight transpose + hi/lo split =========================
// Output Wt[Nout, Kout] K-major.  MODE 0: in W[k*Nout + n] (row-major [K,N]).
// MODE 1: QKV layout, in W[(n>>6)*(DIM*HSZ) + k*HSZ + (n&63)], Kout==DIM.
template<int MODE>
__global__ __launch_bounds__(256)
void wconv_kernel(const float* __restrict__ W, __nv_bfloat16* __restrict__ Wh,
                  __nv_bfloat16* __restrict__ Wl, int Nout, int Kout)
{
    __shared__ float t[32][33];
    const int k0 = blockIdx.x * 32, n0 = blockIdx.y * 32;
    const int tx = threadIdx.x & 31, ty = threadIdx.x >> 5;  // 32 x 8
    #pragma unroll
    for (int j = 0; j < 4; j++) {
        int k = k0 + ty + j * 8;
        int n = n0 + tx;
        float v;
        if (MODE == 0) v = W[(size_t)k * Nout + n];
        else           v = W[(size_t)(n >> 6) * (DIM * HSZ) + (size_t)k * HSZ + (n & 63)];
        t[ty + j * 8][tx] = v;
    }
    __syncthreads();
    #pragma unroll
    for (int j = 0; j < 4; j++) {
        int n = n0 + ty + j * 8;
        int k = k0 + tx;
        float v = t[tx][ty + j * 8];
        __nv_bfloat16 h = __float2bfloat16(v);
        Wh[(size_t)n * Kout + k] = h;
        Wl[(size_t)n * Kout + k] = __float2bfloat16(v - __bfloat162float(h));
    }
}

// ============================ LayerNorm (bf16 hi/lo out) =====================
__global__ __launch_bounds__(256)
void ln_kernel(const float* __restrict__ x, const float* __restrict__ g,
               const float* __restrict__ b,
               __nv_bfloat16* __restrict__ yh, __nv_bfloat16* __restrict__ yl)
{
    const int row = blockIdx.x;
    const int tid = threadIdx.x;
    const float* xr = x + (size_t)row * DIM;

    float4 v = *(const float4*)(xr + tid * 4);
    float s  = v.x + v.y + v.z + v.w;
    float ss = v.x*v.x + v.y*v.y + v.z*v.z + v.w*v.w;
    #pragma unroll
    for (int off = 16; off >= 1; off >>= 1) {
        s  += __shfl_xor_sync(0xffffffffu, s,  off);
        ss += __shfl_xor_sync(0xffffffffu, ss, off);
    }
    __shared__ float sbuf[8], ssbuf[8];
    const int w = tid >> 5, l = tid & 31;
    if (l == 0) { sbuf[w] = s; ssbuf[w] = ss; }
    __syncthreads();
    float st = 0.f, sst = 0.f;
    #pragma unroll
    for (int i = 0; i < 8; i++) { st += sbuf[i]; sst += ssbuf[i]; }
    const float mean = st * (1.0f / DIM);
    const float var  = sst * (1.0f / DIM) - mean * mean;
    const float rstd = rsqrtf(var + 1e-5f);

    float4 gg = *(const float4*)(g + tid * 4);
    float4 bb = *(const float4*)(b + tid * 4);
    float o0 = (v.x - mean) * rstd * gg.x + bb.x;
    float o1 = (v.y - mean) * rstd * gg.y + bb.y;
    float o2 = (v.z - mean) * rstd * gg.z + bb.z;
    float o3 = (v.w - mean) * rstd * gg.w + bb.w;

    __nv_bfloat16 h0 = __float2bfloat16(o0), h1 = __float2bfloat16(o1);
    __nv_bfloat16 h2 = __float2bfloat16(o2), h3 = __float2bfloat16(o3);
    __nv_bfloat162 hp0; hp0.x = h0; hp0.y = h1;
    __nv_bfloat162 hp1; hp1.x = h2; hp1.y = h3;
    __nv_bfloat162 lp0; lp0.x = __float2bfloat16(o0 - __bfloat162float(h0));
                        lp0.y = __float2bfloat16(o1 - __bfloat162float(h1));
    __nv_bfloat162 lp1; lp1.x = __float2bfloat16(o2 - __bfloat162float(h2));
                        lp1.y = __float2bfloat16(o3 - __bfloat162float(h3));
    size_t base = (size_t)row * DIM + tid * 4;
    *(__nv_bfloat162*)(yh + base)     = hp0;
    *(__nv_bfloat162*)(yh + base + 2) = hp1;
    *(__nv_bfloat162*)(yl + base)     = lp0;
    *(__nv_bfloat162*)(yl + base + 2) = lp1;
}

// ==================== mma.sync bf16-split GEMM ===============================
// C[M,N] = A[M,K] @ Wt[N,K]^T with A,B given as bf16 hi/lo pairs.
// 128x128 tile, BK=32, 8 warps (2x4), warp tile 64x32, m16n8k16 fragments.
// 3 passes: Ah*Bh + Ah*Bl + Al*Bh (lo*lo dropped).
// EPI: 0 = fp32 C; 1 = relu(acc+bias) -> Chi/Clo bf16; 2 = acc+bias+res -> fp32.
#define BK 32
#define SSTRIDE 40                       // bf16 elems per smem row (80 B)
#define TILE_ELEMS (128 * SSTRIDE)       // 5120
#define STAGE_ELEMS (4 * TILE_ELEMS)     // 20480 elems = 40960 B
#define GEMM_SMEM_BYTES (2 * STAGE_ELEMS * 2)   // 81920

template<int EPI>
__global__ __launch_bounds__(256)
void mma_gemm(const __nv_bfloat16* __restrict__ Ah, const __nv_bfloat16* __restrict__ Al,
              const __nv_bfloat16* __restrict__ Bh, const __nv_bfloat16* __restrict__ Bl,
              const float* __restrict__ bias, const float* __restrict__ res,
              float* __restrict__ Cf,
              __nv_bfloat16* __restrict__ Chi, __nv_bfloat16* __restrict__ Clo,
              int M, int N, int K)
{
    extern __shared__ __align__(16) char sm_raw[];
    const uint32_t sbase = smem_to_u32(sm_raw);

    const int tid  = threadIdx.x;
    const int lane = tid & 31;
    const int wid  = tid >> 5;
    const int wr   = wid >> 2;           // 0..1
    const int wc   = wid & 3;            // 0..3
    const int m0 = blockIdx.y * 128;
    const int n0 = blockIdx.x * 128;

    // global->smem load mapping: per tile, thread loads row tid>>1, 32B at (tid&1)*16
    const int lrow = tid >> 1;
    const int lkf  = (tid & 1) * 16;

    const __nv_bfloat16* gA[2] = {Ah, Al};
    const __nv_bfloat16* gB[2] = {Bh, Bl};

    auto stage_load = [&](int c, int buf) {
        const int k0 = c * BK;
        const uint32_t s0 = sbase + (uint32_t)buf * (STAGE_ELEMS * 2);
        const uint32_t soff = (uint32_t)(lrow * SSTRIDE + lkf) * 2;
        #pragma unroll
        for (int t = 0; t < 2; t++) {
            const __nv_bfloat16* gp = gA[t] + (size_t)(m0 + lrow) * K + k0 + lkf;
            uint32_t sa = s0 + t * (TILE_ELEMS * 2) + soff;
            cp16(sa, gp); cp16(sa + 16, gp + 8);
        }
        #pragma unroll
        for (int t = 0; t < 2; t++) {
            const __nv_bfloat16* gp = gB[t] + (size_t)(n0 + lrow) * K + k0 + lkf;
            uint32_t sa = s0 + (2 + t) * (TILE_ELEMS * 2) + soff;
            cp16(sa, gp); cp16(sa + 16, gp + 8);
        }
        cp_commit();
    };

    float acc[16][4];
    #pragma unroll
    for (int i = 0; i < 16; i++)
        #pragma unroll
        for (int j = 0; j < 4; j++) acc[i][j] = 0.f;

    // per-lane ldmatrix address components
    const int a_mr = wr * 64 + (lane & 7) + ((lane >> 3) & 1) * 8;  // + mf*16
    const int a_kc = (lane >> 4) * 8;                               // + ks*16
    const int b_nr = wc * 32 + (lane & 7) + (lane >> 4) * 8;        // + nfp*16
    const int b_kc = ((lane >> 3) & 1) * 8;                         // + ks*16

    const int nc = K / BK;
    stage_load(0, 0);

    for (int c = 0; c < nc; c++) {
        if (c + 1 < nc) { stage_load(c + 1, (c + 1) & 1); cp_wait1(); }
        else            { cp_wait0(); }
        __syncthreads();

        const uint32_t aH = sbase + (uint32_t)(c & 1) * (STAGE_ELEMS * 2);
        const uint32_t aL = aH + TILE_ELEMS * 2;
        const uint32_t bH = aH + 2 * TILE_ELEMS * 2;
        const uint32_t bL = aH + 3 * TILE_ELEMS * 2;

        #pragma unroll
        for (int ks = 0; ks < 2; ks++) {
            uint32_t ah[4][4], al[4][4], bh[4][2], bl[4][2];
            #pragma unroll
            for (int mf = 0; mf < 4; mf++) {
                uint32_t off = (uint32_t)((a_mr + mf * 16) * SSTRIDE + a_kc + ks * 16) * 2;
                ldsm4(aH + off, ah[mf]);
                ldsm4(aL + off, al[mf]);
            }
            #pragma unroll
            for (int nfp = 0; nfp < 2; nfp++) {
                uint32_t off = (uint32_t)((b_nr + nfp * 16) * SSTRIDE + b_kc + ks * 16) * 2;
                uint32_t r[4];
                ldsm4(bH + off, r);
                bh[2*nfp][0] = r[0]; bh[2*nfp][1] = r[1];
                bh[2*nfp+1][0] = r[2]; bh[2*nfp+1][1] = r[3];
                ldsm4(bL + off, r);
                bl[2*nfp][0] = r[0]; bl[2*nfp][1] = r[1];
                bl[2*nfp+1][0] = r[2]; bl[2*nfp+1][1] = r[3];
            }
            #pragma unroll
            for (int mf = 0; mf < 4; mf++)
                #pragma unroll
                for (int nf = 0; nf < 4; nf++)
                    mma16816(acc[mf*4+nf], ah[mf], bh[nf]);
            #pragma unroll
            for (int mf = 0; mf < 4; mf++)
                #pragma unroll
                for (int nf = 0; nf < 4; nf++)
                    mma16816(acc[mf*4+nf], ah[mf], bl[nf]);
            #pragma unroll
            for (int mf = 0; mf < 4; mf++)
                #pragma unroll
                for (int nf = 0; nf < 4; nf++)
                    mma16816(acc[mf*4+nf], al[mf], bh[nf]);
        }
        __syncthreads();
    }

    // ---------------- epilogue ----------------
    const int lr = lane >> 2;
    const int lc = (lane & 3) * 2;
    #pragma unroll
    for (int mf = 0; mf < 4; mf++) {
        #pragma unroll
        for (int nf = 0; nf < 4; nf++) {
            const int row = m0 + wr * 64 + mf * 16 + lr;
            const int col = n0 + wc * 32 + nf * 8 + lc;
            const float* cc = acc[mf*4+nf];
            if (EPI == 0) {
                float2 v0 = make_float2(cc[0], cc[1]);
                float2 v1 = make_float2(cc[2], cc[3]);
                *(float2*)(Cf + (size_t)row * N + col)       = v0;
                *(float2*)(Cf + (size_t)(row + 8) * N + col) = v1;
            } else if (EPI == 2) {
                float2 bb = *(const float2*)(bias + col);
                float2 r0 = *(const float2*)(res + (size_t)row * N + col);
                float2 r1 = *(const float2*)(res + (size_t)(row + 8) * N + col);
                float2 v0 = make_float2(cc[0] + bb.x + r0.x, cc[1] + bb.y + r0.y);
                float2 v1 = make_float2(cc[2] + bb.x + r1.x, cc[3] + bb.y + r1.y);
                *(float2*)(Cf + (size_t)row * N + col)       = v0;
                *(float2*)(Cf + (size_t)(row + 8) * N + col) = v1;
            } else {
                float2 bb = *(const float2*)(bias + col);
                float v0 = fmaxf(cc[0] + bb.x, 0.f);
                float v1 = fmaxf(cc[1] + bb.y, 0.f);
                float v2 = fmaxf(cc[2] + bb.x, 0.f);
                float v3 = fmaxf(cc[3] + bb.y, 0.f);
                __nv_bfloat16 h0 = __float2bfloat16(v0), h1 = __float2bfloat16(v1);
                __nv_bfloat16 h2 = __float2bfloat16(v2), h3 = __float2bfloat16(v3);
                __nv_bfloat162 hp0; hp0.x = h0; hp0.y = h1;
                __nv_bfloat162 hp1; hp1.x = h2; hp1.y = h3;
                __nv_bfloat162 lp0;
                lp0.x = __float2bfloat16(v0 - __bfloat162float(h0));
                lp0.y = __float2bfloat16(v1 - __bfloat162float(h1));
                __nv_bfloat162 lp1;
                lp1.x = __float2bfloat16(v2 - __bfloat162float(h2));
                lp1.y = __float2bfloat16(v3 - __bfloat162float(h3));
                *(__nv_bfloat162*)(Chi + (size_t)row * N + col)       = hp0;
                *(__nv_bfloat162*)(Clo + (size_t)row * N + col)       = lp0;
                *(__nv_bfloat162*)(Chi + (size_t)(row + 8) * N + col) = hp1;
                *(__nv_bfloat162*)(Clo + (size_t)(row + 8) * N + col) = lp1;
            }
        }
    }
}

// ============================ Flash attention ================================
// grid: (SEQ/64, HEADS, BATCH), block 256. Q/K/V fp32 in [B,T,H*HS] layout.
// Output written as bf16 hi/lo (input to Wo GEMM).
#define ATTN_SMEM_FLOATS (3 * 64 * 64 + 64 * 68)
#define ATTN_SMEM_BYTES  (ATTN_SMEM_FLOATS * 4)

__global__ __launch_bounds__(256)
void attn_kernel(const float* __restrict__ Q, const float* __restrict__ Kp,
                 const float* __restrict__ V,
                 __nv_bfloat16* __restrict__ Oh, __nv_bfloat16* __restrict__ Ol)
{
    extern __shared__ float sm[];
    float* Qs = sm;                  // [k][r]  64x64
    float* Ks = sm + 4096;           // [k][c]  64x64
    float* Vs = sm + 8192;           // [kk][j] 64x64
    float* Ps = sm + 12288;          // [kk][r] 64x68 (padded)

    const int tid = threadIdx.x;
    const int tx = tid & 15;
    const int ty = tid >> 4;
    const int qb = blockIdx.x * 64;
    const int h  = blockIdx.y;
    const int b  = blockIdx.z;

    const size_t baseQ = ((size_t)(b * SEQ + qb)) * DIM + h * HSZ;

    #pragma unroll
    for (int it = 0; it < 4; it++) {
        int i = tid + it * 256;
        int rr = i >> 4;
        int k4 = (i & 15) << 2;
        float4 qv = *(const float4*)(Q + baseQ + (size_t)rr * DIM + k4);
        Qs[(k4 + 0) * 64 + rr] = qv.x;
        Qs[(k4 + 1) * 64 + rr] = qv.y;
        Qs[(k4 + 2) * 64 + rr] = qv.z;
        Qs[(k4 + 3) * 64 + rr] = qv.w;
    }

    float m_run[4], l_run[4], acc[4][4];
    #pragma unroll
    for (int i = 0; i < 4; i++) {
        m_run[i] = -1e30f; l_run[i] = 0.f;
        #pragma unroll
        for (int j = 0; j < 4; j++) acc[i][j] = 0.f;
    }

    for (int kc = 0; kc < SEQ; kc += 64) {
        __syncthreads();
        const size_t baseK = ((size_t)(b * SEQ + kc)) * DIM + h * HSZ;
        #pragma unroll
        for (int it = 0; it < 4; it++) {
            int i = tid + it * 256;
            int rr = i >> 4;
            int k4 = (i & 15) << 2;
            float4 kv = *(const float4*)(Kp + baseK + (size_t)rr * DIM + k4);
            Ks[(k4 + 0) * 64 + rr] = kv.x;
            Ks[(k4 + 1) * 64 + rr] = kv.y;
            Ks[(k4 + 2) * 64 + rr] = kv.z;
            Ks[(k4 + 3) * 64 + rr] = kv.w;
            float4 vv = *(const float4*)(V + baseK + (size_t)rr * DIM + k4);
            *(float4*)&Vs[rr * 64 + k4] = vv;
        }
        __syncthreads();

        float s4[4][4];
        #pragma unroll
        for (int i = 0; i < 4; i++)
            #pragma unroll
            for (int j = 0; j < 4; j++) s4[i][j] = 0.f;
        #pragma unroll 8
        for (int k = 0; k < 64; k++) {
            float4 qa = *(const float4*)&Qs[k * 64 + ty * 4];
            float4 kb = *(const float4*)&Ks[k * 64 + tx * 4];
            float aq[4] = {qa.x, qa.y, qa.z, qa.w};
            float bk[4] = {kb.x, kb.y, kb.z, kb.w};
            #pragma unroll
            for (int i = 0; i < 4; i++)
                #pragma unroll
                for (int j = 0; j < 4; j++)
                    s4[i][j] = fmaf(aq[i], bk[j], s4[i][j]);
        }
        #pragma unroll
        for (int i = 0; i < 4; i++)
            #pragma unroll
            for (int j = 0; j < 4; j++) s4[i][j] *= 0.125f;

        float mloc[4];
        #pragma unroll
        for (int i = 0; i < 4; i++)
            mloc[i] = fmaxf(fmaxf(s4[i][0], s4[i][1]), fmaxf(s4[i][2], s4[i][3]));
        #pragma unroll
        for (int off = 8; off >= 1; off >>= 1)
            #pragma unroll
            for (int i = 0; i < 4; i++)
                mloc[i] = fmaxf(mloc[i], __shfl_xor_sync(0xffffffffu, mloc[i], off));

        float alpha[4], mnew[4], lloc[4];
        #pragma unroll
        for (int i = 0; i < 4; i++) {
            mnew[i]  = fmaxf(m_run[i], mloc[i]);
            alpha[i] = __expf(m_run[i] - mnew[i]);
            m_run[i] = mnew[i];
            lloc[i]  = 0.f;
        }

        float p[4][4];
        #pragma unroll
        for (int i = 0; i < 4; i++)
            #pragma unroll
            for (int j = 0; j < 4; j++) {
                p[i][j] = __expf(s4[i][j] - mnew[i]);
                lloc[i] += p[i][j];
            }
        #pragma unroll
        for (int off = 8; off >= 1; off >>= 1)
            #pragma unroll
            for (int i = 0; i < 4; i++)
                lloc[i] += __shfl_xor_sync(0xffffffffu, lloc[i], off);
        #pragma unroll
        for (int i = 0; i < 4; i++) {
            l_run[i] = l_run[i] * alpha[i] + lloc[i];
            #pragma unroll
            for (int j = 0; j < 4; j++) acc[i][j] *= alpha[i];
        }

        #pragma unroll
        for (int j = 0; j < 4; j++) {
            float4 pv = make_float4(p[0][j], p[1][j], p[2][j], p[3][j]);
            *(float4*)&Ps[(tx * 4 + j) * 68 + ty * 4] = pv;
        }
        __syncthreads();

        #pragma unroll 8
        for (int kk = 0; kk < 64; kk++) {
            float4 pa = *(const float4*)&Ps[kk * 68 + ty * 4];
            float4 vb = *(const float4*)&Vs[kk * 64 + tx * 4];
            float ap[4] = {pa.x, pa.y, pa.z, pa.w};
            float bv[4] = {vb.x, vb.y, vb.z, vb.w};
            #pragma unroll
            for (int i = 0; i < 4; i++)
                #pragma unroll
                for (int j = 0; j < 4; j++)
                    acc[i][j] = fmaf(ap[i], bv[j], acc[i][j]);
        }
    }

    #pragma unroll
    for (int i = 0; i < 4; i++) {
        const float rl = 1.0f / l_run[i];
        float o0 = acc[i][0] * rl, o1 = acc[i][1] * rl;
        float o2 = acc[i][2] * rl, o3 = acc[i][3] * rl;
        __nv_bfloat16 h0 = __float2bfloat16(o0), h1 = __float2bfloat16(o1);
        __nv_bfloat16 h2 = __float2bfloat16(o2), h3 = __float2bfloat16(o3);
        __nv_bfloat162 hp0; hp0.x = h0; hp0.y = h1;
        __nv_bfloat162 hp1; hp1.x = h2; hp1.y = h3;
        __nv_bfloat162 lp0; lp0.x = __float2bfloat16(o0 - __bfloat162float(h0));
                            lp0.y = __float2bfloat16(o1 - __bfloat162float(h1));
        __nv_bfloat162 lp1; lp1.x = __float2bfloat16(o2 - __bfloat162float(h2));
                            lp1.y = __float2bfloat16(o3 - __bfloat162float(h3));
        size_t base = baseQ + (size_t)(ty * 4 + i) * DIM + tx * 4;
        *(__nv_bfloat162*)(Oh + base)     = hp0;
        *(__nv_bfloat162*)(Oh + base + 2) = hp1;
        *(__nv_bfloat162*)(Ol + base)     = lp0;
        *(__nv_bfloat162*)(Ol + base + 2) = lp1;
    }
}

// ============================ launch =========================================
extern "C" void kernel_launch(void* const* d_in, const int* in_sizes, int n_in,
                              void* d_out, int out_size)
{
    const float* x     = (const float*)d_in[0];
    const float* Wq    = (const float*)d_in[1];
    const float* Wk    = (const float*)d_in[2];
    const float* Wv    = (const float*)d_in[3];
    const float* Wo    = (const float*)d_in[4];
    const float* bo    = (const float*)d_in[5];
    const float* W1    = (const float*)d_in[6];
    const float* b1    = (const float*)d_in[7];
    const float* W2    = (const float*)d_in[8];
    const float* b2    = (const float*)d_in[9];
    const float* ln1_g = (const float*)d_in[10];
    const float* ln1_b = (const float*)d_in[11];
    const float* ln2_g = (const float*)d_in[12];
    const float* ln2_b = (const float*)d_in[13];
    float* out = (float*)d_out;

    float *pq, *pk, *pv, *px1;
    __nv_bfloat16 *phh, *phl, *patth, *pattl, *pffh, *pffl;
    __nv_bfloat16 *pwqh, *pwql, *pwkh, *pwkl, *pwvh, *pwvl;
    __nv_bfloat16 *pwoh, *pwol, *pw1h, *pw1l, *pw2h, *pw2l;
    cudaGetSymbolAddress((void**)&pq,   g_q);
    cudaGetSymbolAddress((void**)&pk,   g_k);
    cudaGetSymbolAddress((void**)&pv,   g_v);
    cudaGetSymbolAddress((void**)&px1,  g_x1);
    cudaGetSymbolAddress((void**)&phh,  g_hh);
    cudaGetSymbolAddress((void**)&phl,  g_hl);
    cudaGetSymbolAddress((void**)&patth, g_atth);
    cudaGetSymbolAddress((void**)&pattl, g_attl);
    cudaGetSymbolAddress((void**)&pffh, g_ffh);
    cudaGetSymbolAddress((void**)&pffl, g_ffl);
    cudaGetSymbolAddress((void**)&pwqh, g_wqh);
    cudaGetSymbolAddress((void**)&pwql, g_wql);
    cudaGetSymbolAddress((void**)&pwkh, g_wkh);
    cudaGetSymbolAddress((void**)&pwkl, g_wkl);
    cudaGetSymbolAddress((void**)&pwvh, g_wvh);
    cudaGetSymbolAddress((void**)&pwvl, g_wvl);
    cudaGetSymbolAddress((void**)&pwoh, g_woh);
    cudaGetSymbolAddress((void**)&pwol, g_wol);
    cudaGetSymbolAddress((void**)&pw1h, g_w1h);
    cudaGetSymbolAddress((void**)&pw1l, g_w1l);
    cudaGetSymbolAddress((void**)&pw2h, g_w2h);
    cudaGetSymbolAddress((void**)&pw2l, g_w2l);

    cudaFuncSetAttribute(attn_kernel, cudaFuncAttributeMaxDynamicSharedMemorySize,
                         ATTN_SMEM_BYTES);
    cudaFuncSetAttribute(mma_gemm<0>, cudaFuncAttributeMaxDynamicSharedMemorySize,
                         GEMM_SMEM_BYTES);
    cudaFuncSetAttribute(mma_gemm<1>, cudaFuncAttributeMaxDynamicSharedMemorySize,
                         GEMM_SMEM_BYTES);
    cudaFuncSetAttribute(mma_gemm<2>, cudaFuncAttributeMaxDynamicSharedMemorySize,
                         GEMM_SMEM_BYTES);

    // 0) weight transpose + hi/lo split
    wconv_kernel<1><<<dim3(DIM/32, DIM/32), 256>>>(Wq, pwqh, pwql, DIM, DIM);
    wconv_kernel<1><<<dim3(DIM/32, DIM/32), 256>>>(Wk, pwkh, pwkl, DIM, DIM);
    wconv_kernel<1><<<dim3(DIM/32, DIM/32), 256>>>(Wv, pwvh, pwvl, DIM, DIM);
    wconv_kernel<0><<<dim3(DIM/32, DIM/32), 256>>>(Wo, pwoh, pwol, DIM, DIM);
    wconv_kernel<0><<<dim3(DIM/32, FFDIM/32), 256>>>(W1, pw1h, pw1l, FFDIM, DIM);
    wconv_kernel<0><<<dim3(FFDIM/32, DIM/32), 256>>>(W2, pw2h, pw2l, DIM, FFDIM);

    // 1) h = LN1(x) -> bf16 hi/lo
    ln_kernel<<<ROWS, 256>>>(x, ln1_g, ln1_b, phh, phl);

    // 2) Q,K,V projections (fp32 out)
    dim3 gP(DIM / 128, ROWS / 128);      // (8, 32)
    mma_gemm<0><<<gP, 256, GEMM_SMEM_BYTES>>>(phh, phl, pwqh, pwql, nullptr, nullptr,
                                              pq, nullptr, nullptr, ROWS, DIM, DIM);
    mma_gemm<0><<<gP, 256, GEMM_SMEM_BYTES>>>(phh, phl, pwkh, pwkl, nullptr, nullptr,
                                              pk, nullptr, nullptr, ROWS, DIM, DIM);
    mma_gemm<0><<<gP, 256, GEMM_SMEM_BYTES>>>(phh, phl, pwvh, pwvl, nullptr, nullptr,
                                              pv, nullptr, nullptr, ROWS, DIM, DIM);

    // 3) attention -> bf16 hi/lo
    dim3 gAttn(SEQ / 64, HEADS, BATCH);
    attn_kernel<<<gAttn, 256, ATTN_SMEM_BYTES>>>(pq, pk, pv, patth, pattl);

    // 4) x1 = x + attn @ Wo + bo (fp32)
    mma_gemm<2><<<gP, 256, GEMM_SMEM_BYTES>>>(patth, pattl, pwoh, pwol, bo, x,
                                              px1, nullptr, nullptr, ROWS, DIM, DIM);

    // 5) h2 = LN2(x1) -> bf16 hi/lo
    ln_kernel<<<ROWS, 256>>>(px1, ln2_g, ln2_b, phh, phl);

    // 6) ff = relu(h2 @ W1 + b1) -> bf16 hi/lo
    dim3 gF(FFDIM / 128, ROWS / 128);    // (32, 32)
    mma_gemm<1><<<gF, 256, GEMM_SMEM_BYTES>>>(phh, phl, pw1h, pw1l, b1, nullptr,
                                              nullptr, pffh, pffl, ROWS, FFDIM, DIM);

    // 7) out = x1 + ff @ W2 + b2 (fp32)
    mma_gemm<2><<<gP, 256, GEMM_SMEM_BYTES>>>(pffh, pffl, pw2h, pw2l, b2, px1,
                                              out, nullptr, nullptr, ROWS, DIM, FFDIM);
}

// round 5
// speedup vs baseline: 2.4644x; 1.6835x over previous
#include <cuda_runtime.h>
#include <cuda_bf16.h>
#include <cuda_fp16.h>
#include <cstdint>
#include <cstddef>

// Problem constants
#define BATCH 2
#define SEQ   2048
#define DIM   1024
#define HEADS 16
#define HSZ   64
#define ROWS  (BATCH*SEQ)          // 4096
#define FFDIM (4*DIM)              // 4096

// ======================= PTX helpers (family-safe only) ======================
__device__ __forceinline__ uint32_t smem_to_u32(const void* smem_ptr) {
    uint32_t addr;
    asm("{ .reg .u64 tmp; cvta.to.shared.u64 tmp, %1; cvt.u32.u64 %0, tmp; }"
        : "=r"(addr) : "l"(smem_ptr));
    return addr;
}

__device__ __forceinline__ void cp16(uint32_t saddr, const void* gptr) {
    asm volatile("cp.async.cg.shared.global [%0], [%1], 16;"
                 :: "r"(saddr), "l"(gptr) : "memory");
}
__device__ __forceinline__ void cp_commit() {
    asm volatile("cp.async.commit_group;" ::: "memory");
}
__device__ __forceinline__ void cp_wait1() {
    asm volatile("cp.async.wait_group 1;" ::: "memory");
}
__device__ __forceinline__ void cp_wait0() {
    asm volatile("cp.async.wait_group 0;" ::: "memory");
}

__device__ __forceinline__ void ldsm4(uint32_t addr, uint32_t* r) {
    asm volatile("ldmatrix.sync.aligned.m8n8.x4.shared.b16 {%0,%1,%2,%3}, [%4];"
                 : "=r"(r[0]), "=r"(r[1]), "=r"(r[2]), "=r"(r[3]) : "r"(addr));
}
__device__ __forceinline__ void ldsm4t(uint32_t addr, uint32_t* r) {
    asm volatile("ldmatrix.sync.aligned.m8n8.x4.trans.shared.b16 {%0,%1,%2,%3}, [%4];"
                 : "=r"(r[0]), "=r"(r[1]), "=r"(r[2]), "=r"(r[3]) : "r"(addr));
}

__device__ __forceinline__ void mma16816(float* c, const uint32_t* a, const uint32_t* b) {
    asm volatile(
        "mma.sync.aligned.m16n8k16.row.col.f32.bf16.bf16.f32 "
        "{%0,%1,%2,%3}, {%4,%5,%6,%7}, {%8,%9}, {%0,%1,%2,%3};"
        : "+f"(c[0]), "+f"(c[1]), "+f"(c[2]), "+f"(c[3])
        : "r"(a[0]), "r"(a[1]), "r"(a[2]), "r"(a[3]), "r"(b[0]), "r"(b[1]));
}
__device__ __forceinline__ void mma16816h(float* c, const uint32_t* a, const uint32_t* b) {
    asm volatile(
        "mma.sync.aligned.m16n8k16.row.col.f32.f16.f16.f32 "
        "{%0,%1,%2,%3}, {%4,%5,%6,%7}, {%8,%9}, {%0,%1,%2,%3};"
        : "+f"(c[0]), "+f"(c[1]), "+f"(c[2]), "+f"(c[3])
        : "r"(a[0]), "r"(a[1]), "r"(a[2]), "r"(a[3]), "r"(b[0]), "r"(b[1]));
}

// pack two fp32 (hi goes to upper f16, lo to lower f16) then exp2 both halves
__device__ __forceinline__ uint32_t packex2(float hi, float lo) {
    uint32_t d;
    asm("cvt.rn.f16x2.f32 %0, %1, %2;" : "=r"(d) : "f"(hi), "f"(lo));
    asm("ex2.approx.f16x2 %0, %0;" : "+r"(d));
    return d;
}
__device__ __forceinline__ float ex2f(float x) {
    float r; asm("ex2.approx.ftz.f32 %0, %1;" : "=f"(r) : "f"(x)); return r;
}

// ---------------- scratch (static device arrays; no allocations) -------------
__device__ float g_x1 [ROWS * DIM];     // x + attn_out (fp32)

__device__ __nv_bfloat16 g_hh [ROWS * DIM];     // LN output hi (ln1 / ln2 reuse)
__device__ __nv_bfloat16 g_hl [ROWS * DIM];     // LN output lo
__device__ __nv_bfloat16 g_qhh[ROWS * DIM],  g_qll[ROWS * DIM];
__device__ __nv_bfloat16 g_khh[ROWS * DIM],  g_kll[ROWS * DIM];
__device__ __half        g_vf [ROWS * DIM];
__device__ __nv_bfloat16 g_atth[ROWS * DIM];
__device__ __nv_bfloat16 g_attl[ROWS * DIM];
__device__ __nv_bfloat16 g_ffh [ROWS * FFDIM];
__device__ __nv_bfloat16 g_ffl [ROWS * FFDIM];

// weights, transposed to [N, K] K-major, hi/lo split
__device__ __nv_bfloat16 g_wqh[DIM * DIM],   g_wql[DIM * DIM];
__device__ __nv_bfloat16 g_wkh[DIM * DIM],   g_wkl[DIM * DIM];
__device__ __nv_bfloat16 g_wvh[DIM * DIM],   g_wvl[DIM * DIM];
__device__ __nv_bfloat16 g_woh[DIM * DIM],   g_wol[DIM * DIM];
__device__ __nv_bfloat16 g_w1h[FFDIM * DIM], g_w1l[FFDIM * DIM];
__device__ __nv_bfloat16 g_w2h[DIM * FFDIM], g_w2l[DIM * FFDIM];

// ==================== weight transpose + hi/lo split =========================
template<int MODE>
__global__ __launch_bounds__(256)
void wconv_kernel(const float* __restrict__ W, __nv_bfloat16* __restrict__ Wh,
                  __nv_bfloat16* __restrict__ Wl, int Nout, int Kout)
{
    __shared__ float t[32][33];
    const int k0 = blockIdx.x * 32, n0 = blockIdx.y * 32;
    const int tx = threadIdx.x & 31, ty = threadIdx.x >> 5;  // 32 x 8
    #pragma unroll
    for (int j = 0; j < 4; j++) {
        int k = k0 + ty + j * 8;
        int n = n0 + tx;
        float v;
        if (MODE == 0) v = W[(size_t)k * Nout + n];
        else           v = W[(size_t)(n >> 6) * (DIM * HSZ) + (size_t)k * HSZ + (n & 63)];
        t[ty + j * 8][tx] = v;
    }
    __syncthreads();
    #pragma unroll
    for (int j = 0; j < 4; j++) {
        int n = n0 + ty + j * 8;
        int k = k0 + tx;
        float v = t[tx][ty + j * 8];
        __nv_bfloat16 h = __float2bfloat16(v);
        Wh[(size_t)n * Kout + k] = h;
        Wl[(size_t)n * Kout + k] = __float2bfloat16(v - __bfloat162float(h));
    }
}

// ============================ LayerNorm (bf16 hi/lo out) =====================
__global__ __launch_bounds__(256)
void ln_kernel(const float* __restrict__ x, const float* __restrict__ g,
               const float* __restrict__ b,
               __nv_bfloat16* __restrict__ yh, __nv_bfloat16* __restrict__ yl)
{
    const int row = blockIdx.x;
    const int tid = threadIdx.x;
    const float* xr = x + (size_t)row * DIM;

    float4 v = *(const float4*)(xr + tid * 4);
    float s  = v.x + v.y + v.z + v.w;
    float ss = v.x*v.x + v.y*v.y + v.z*v.z + v.w*v.w;
    #pragma unroll
    for (int off = 16; off >= 1; off >>= 1) {
        s  += __shfl_xor_sync(0xffffffffu, s,  off);
        ss += __shfl_xor_sync(0xffffffffu, ss, off);
    }
    __shared__ float sbuf[8], ssbuf[8];
    const int w = tid >> 5, l = tid & 31;
    if (l == 0) { sbuf[w] = s; ssbuf[w] = ss; }
    __syncthreads();
    float st = 0.f, sst = 0.f;
    #pragma unroll
    for (int i = 0; i < 8; i++) { st += sbuf[i]; sst += ssbuf[i]; }
    const float mean = st * (1.0f / DIM);
    const float var  = sst * (1.0f / DIM) - mean * mean;
    const float rstd = rsqrtf(var + 1e-5f);

    float4 gg = *(const float4*)(g + tid * 4);
    float4 bb = *(const float4*)(b + tid * 4);
    float o0 = (v.x - mean) * rstd * gg.x + bb.x;
    float o1 = (v.y - mean) * rstd * gg.y + bb.y;
    float o2 = (v.z - mean) * rstd * gg.z + bb.z;
    float o3 = (v.w - mean) * rstd * gg.w + bb.w;

    __nv_bfloat16 h0 = __float2bfloat16(o0), h1 = __float2bfloat16(o1);
    __nv_bfloat16 h2 = __float2bfloat16(o2), h3 = __float2bfloat16(o3);
    __nv_bfloat162 hp0; hp0.x = h0; hp0.y = h1;
    __nv_bfloat162 hp1; hp1.x = h2; hp1.y = h3;
    __nv_bfloat162 lp0; lp0.x = __float2bfloat16(o0 - __bfloat162float(h0));
                        lp0.y = __float2bfloat16(o1 - __bfloat162float(h1));
    __nv_bfloat162 lp1; lp1.x = __float2bfloat16(o2 - __bfloat162float(h2));
                        lp1.y = __float2bfloat16(o3 - __bfloat162float(h3));
    size_t base = (size_t)row * DIM + tid * 4;
    *(__nv_bfloat162*)(yh + base)     = hp0;
    *(__nv_bfloat162*)(yh + base + 2) = hp1;
    *(__nv_bfloat162*)(yl + base)     = lp0;
    *(__nv_bfloat162*)(yl + base + 2) = lp1;
}

// ==================== mma.sync bf16-split GEMM ===============================
// EPI: 1 = relu(acc+bias) -> Chi/Clo bf16; 2 = acc+bias+res -> fp32;
//      3 = acc -> Chi/Clo bf16;            4 = acc -> Ch fp16.
#define BK 32
#define SSTRIDE 40
#define TILE_ELEMS (128 * SSTRIDE)
#define STAGE_ELEMS (4 * TILE_ELEMS)
#define GEMM_SMEM_BYTES (2 * STAGE_ELEMS * 2)

template<int EPI>
__global__ __launch_bounds__(256)
void mma_gemm(const __nv_bfloat16* __restrict__ Ah, const __nv_bfloat16* __restrict__ Al,
              const __nv_bfloat16* __restrict__ Bh, const __nv_bfloat16* __restrict__ Bl,
              const float* __restrict__ bias, const float* __restrict__ res,
              float* __restrict__ Cf,
              __nv_bfloat16* __restrict__ Chi, __nv_bfloat16* __restrict__ Clo,
              __half* __restrict__ Ch,
              int M, int N, int K)
{
    extern __shared__ __align__(16) char sm_raw[];
    const uint32_t sbase = smem_to_u32(sm_raw);

    const int tid  = threadIdx.x;
    const int lane = tid & 31;
    const int wid  = tid >> 5;
    const int wr   = wid >> 2;
    const int wc   = wid & 3;
    const int m0 = blockIdx.y * 128;
    const int n0 = blockIdx.x * 128;

    const int lrow = tid >> 1;
    const int lkf  = (tid & 1) * 16;

    const __nv_bfloat16* gA[2] = {Ah, Al};
    const __nv_bfloat16* gB[2] = {Bh, Bl};

    auto stage_load = [&](int c, int buf) {
        const int k0 = c * BK;
        const uint32_t s0 = sbase + (uint32_t)buf * (STAGE_ELEMS * 2);
        const uint32_t soff = (uint32_t)(lrow * SSTRIDE + lkf) * 2;
        #pragma unroll
        for (int t = 0; t < 2; t++) {
            const __nv_bfloat16* gp = gA[t] + (size_t)(m0 + lrow) * K + k0 + lkf;
            uint32_t sa = s0 + t * (TILE_ELEMS * 2) + soff;
            cp16(sa, gp); cp16(sa + 16, gp + 8);
        }
        #pragma unroll
        for (int t = 0; t < 2; t++) {
            const __nv_bfloat16* gp = gB[t] + (size_t)(n0 + lrow) * K + k0 + lkf;
            uint32_t sa = s0 + (2 + t) * (TILE_ELEMS * 2) + soff;
            cp16(sa, gp); cp16(sa + 16, gp + 8);
        }
        cp_commit();
    };

    float acc[16][4];
    #pragma unroll
    for (int i = 0; i < 16; i++)
        #pragma unroll
        for (int j = 0; j < 4; j++) acc[i][j] = 0.f;

    const int a_mr = wr * 64 + (lane & 7) + ((lane >> 3) & 1) * 8;
    const int a_kc = (lane >> 4) * 8;
    const int b_nr = wc * 32 + (lane & 7) + (lane >> 4) * 8;
    const int b_kc = ((lane >> 3) & 1) * 8;

    const int nc = K / BK;
    stage_load(0, 0);

    for (int c = 0; c < nc; c++) {
        if (c + 1 < nc) { stage_load(c + 1, (c + 1) & 1); cp_wait1(); }
        else            { cp_wait0(); }
        __syncthreads();

        const uint32_t aH = sbase + (uint32_t)(c & 1) * (STAGE_ELEMS * 2);
        const uint32_t aL = aH + TILE_ELEMS * 2;
        const uint32_t bH = aH + 2 * TILE_ELEMS * 2;
        const uint32_t bL = aH + 3 * TILE_ELEMS * 2;

        #pragma unroll
        for (int ks = 0; ks < 2; ks++) {
            uint32_t ah[4][4], al[4][4], bh[4][2], bl[4][2];
            #pragma unroll
            for (int mf = 0; mf < 4; mf++) {
                uint32_t off = (uint32_t)((a_mr + mf * 16) * SSTRIDE + a_kc + ks * 16) * 2;
                ldsm4(aH + off, ah[mf]);
                ldsm4(aL + off, al[mf]);
            }
            #pragma unroll
            for (int nfp = 0; nfp < 2; nfp++) {
                uint32_t off = (uint32_t)((b_nr + nfp * 16) * SSTRIDE + b_kc + ks * 16) * 2;
                uint32_t r[4];
                ldsm4(bH + off, r);
                bh[2*nfp][0] = r[0]; bh[2*nfp][1] = r[1];
                bh[2*nfp+1][0] = r[2]; bh[2*nfp+1][1] = r[3];
                ldsm4(bL + off, r);
                bl[2*nfp][0] = r[0]; bl[2*nfp][1] = r[1];
                bl[2*nfp+1][0] = r[2]; bl[2*nfp+1][1] = r[3];
            }
            #pragma unroll
            for (int mf = 0; mf < 4; mf++)
                #pragma unroll
                for (int nf = 0; nf < 4; nf++)
                    mma16816(acc[mf*4+nf], ah[mf], bh[nf]);
            #pragma unroll
            for (int mf = 0; mf < 4; mf++)
                #pragma unroll
                for (int nf = 0; nf < 4; nf++)
                    mma16816(acc[mf*4+nf], ah[mf], bl[nf]);
            #pragma unroll
            for (int mf = 0; mf < 4; mf++)
                #pragma unroll
                for (int nf = 0; nf < 4; nf++)
                    mma16816(acc[mf*4+nf], al[mf], bh[nf]);
        }
        __syncthreads();
    }

    // ---------------- epilogue ----------------
    const int lr = lane >> 2;
    const int lc = (lane & 3) * 2;
    #pragma unroll
    for (int mf = 0; mf < 4; mf++) {
        #pragma unroll
        for (int nf = 0; nf < 4; nf++) {
            const int row = m0 + wr * 64 + mf * 16 + lr;
            const int col = n0 + wc * 32 + nf * 8 + lc;
            const float* cc = acc[mf*4+nf];
            if (EPI == 2) {
                float2 bb = *(const float2*)(bias + col);
                float2 r0 = *(const float2*)(res + (size_t)row * N + col);
                float2 r1 = *(const float2*)(res + (size_t)(row + 8) * N + col);
                float2 v0 = make_float2(cc[0] + bb.x + r0.x, cc[1] + bb.y + r0.y);
                float2 v1 = make_float2(cc[2] + bb.x + r1.x, cc[3] + bb.y + r1.y);
                *(float2*)(Cf + (size_t)row * N + col)       = v0;
                *(float2*)(Cf + (size_t)(row + 8) * N + col) = v1;
            } else if (EPI == 4) {
                *(__half2*)(Ch + (size_t)row * N + col)       = __floats2half2_rn(cc[0], cc[1]);
                *(__half2*)(Ch + (size_t)(row + 8) * N + col) = __floats2half2_rn(cc[2], cc[3]);
            } else {
                float v0 = cc[0], v1 = cc[1], v2 = cc[2], v3 = cc[3];
                if (EPI == 1) {
                    float2 bb = *(const float2*)(bias + col);
                    v0 = fmaxf(v0 + bb.x, 0.f); v1 = fmaxf(v1 + bb.y, 0.f);
                    v2 = fmaxf(v2 + bb.x, 0.f); v3 = fmaxf(v3 + bb.y, 0.f);
                }
                __nv_bfloat16 h0 = __float2bfloat16(v0), h1 = __float2bfloat16(v1);
                __nv_bfloat16 h2 = __float2bfloat16(v2), h3 = __float2bfloat16(v3);
                __nv_bfloat162 hp0; hp0.x = h0; hp0.y = h1;
                __nv_bfloat162 hp1; hp1.x = h2; hp1.y = h3;
                __nv_bfloat162 lp0;
                lp0.x = __float2bfloat16(v0 - __bfloat162float(h0));
                lp0.y = __float2bfloat16(v1 - __bfloat162float(h1));
                __nv_bfloat162 lp1;
                lp1.x = __float2bfloat16(v2 - __bfloat162float(h2));
                lp1.y = __float2bfloat16(v3 - __bfloat162float(h3));
                *(__nv_bfloat162*)(Chi + (size_t)row * N + col)       = hp0;
                *(__nv_bfloat162*)(Clo + (size_t)row * N + col)       = lp0;
                *(__nv_bfloat162*)(Chi + (size_t)(row + 8) * N + col) = hp1;
                *(__nv_bfloat162*)(Clo + (size_t)(row + 8) * N + col) = lp1;
            }
        }
    }
}

// ==================== mma flash attention ====================================
// grid (SEQ/128, HEADS, BATCH), 256 threads (8 warps, warp w owns rows w*16..+15).
// Q,K bf16 hi/lo (3-pass exact scores), V fp16, P via ex2.approx.f16x2,
// row-sum via ones-column f16 HMMA, online max inside warp quads.
#define QSTR 72
#define SM_QH 0
#define SM_QL (128*QSTR*2)                    // 18432
#define SM_K  (2*128*QSTR*2)                  // 36864 ; buf stride 18432 (Kh + Kl)
#define SM_V  (SM_K + 2*18432)                // 73728 ; buf stride 9216
#define ATTN_SMEM_BYTES (SM_V + 2*9216)       // 92160
#define CEXP 0.1803368801111f                 // log2(e)/8

__global__ __launch_bounds__(256)
void attn_mma_kernel(const __nv_bfloat16* __restrict__ Qh_, const __nv_bfloat16* __restrict__ Ql_,
                     const __nv_bfloat16* __restrict__ Kh_, const __nv_bfloat16* __restrict__ Kl_,
                     const __half* __restrict__ Vf_,
                     __nv_bfloat16* __restrict__ Oh, __nv_bfloat16* __restrict__ Ol)
{
    extern __shared__ __align__(16) char smraw[];
    const uint32_t sb = smem_to_u32(smraw);
    const int tid = threadIdx.x, lane = tid & 31, w = tid >> 5;
    const int h = blockIdx.y, bz = blockIdx.z;
    const int rowbase = bz * SEQ + blockIdx.x * 128;
    const size_t gQrow0 = (size_t)rowbase * DIM + h * HSZ;
    const size_t gKbase = (size_t)bz * SEQ * DIM + h * HSZ;

    // ---- stage Q (grouped with KV tile 0) ----
    {
        int r = tid >> 1, cc = (tid & 1) * 4;
        const char* gq = (const char*)(Qh_ + gQrow0 + (size_t)r * DIM);
        const char* gl = (const char*)(Ql_ + gQrow0 + (size_t)r * DIM);
        uint32_t sh = sb + SM_QH + (uint32_t)(r * QSTR) * 2;
        uint32_t sl = sb + SM_QL + (uint32_t)(r * QSTR) * 2;
        #pragma unroll
        for (int i = 0; i < 4; i++) {
            cp16(sh + (cc + i) * 16, gq + (cc + i) * 16);
            cp16(sl + (cc + i) * 16, gl + (cc + i) * 16);
        }
    }
    auto stageKV = [&](int it, int buf) {
        int r = tid >> 2, c0 = (tid & 3) * 32;
        size_t grow = gKbase + (size_t)(it * 64 + r) * DIM;
        uint32_t kh = sb + SM_K + (uint32_t)buf * 18432 + (uint32_t)(r * QSTR) * 2;
        uint32_t kl = kh + 9216;
        uint32_t vv = sb + SM_V + (uint32_t)buf * 9216 + (uint32_t)(r * QSTR) * 2;
        cp16(kh + c0,      (const char*)(Kh_ + grow) + c0);
        cp16(kh + c0 + 16, (const char*)(Kh_ + grow) + c0 + 16);
        cp16(kl + c0,      (const char*)(Kl_ + grow) + c0);
        cp16(kl + c0 + 16, (const char*)(Kl_ + grow) + c0 + 16);
        cp16(vv + c0,      (const char*)(Vf_ + grow) + c0);
        cp16(vv + c0 + 16, (const char*)(Vf_ + grow) + c0 + 16);
    };
    stageKV(0, 0);
    cp_commit();

    // A-operand lane pattern (Q, and V-trans)
    const int frow = (lane & 7) + ((lane >> 3) & 1) * 8;
    const int fcol = (lane >> 4) * 8;
    // B-operand lane pattern (K, non-trans)  -- FIX vs round 4
    const int kbrow = (lane & 7) + (lane >> 4) * 8;
    const int kbcol = ((lane >> 3) & 1) * 8;

    uint32_t qh[4][4], ql[4][4];
    float acc[8][4], lacc[4];
    #pragma unroll
    for (int i = 0; i < 8; i++)
        #pragma unroll
        for (int j = 0; j < 4; j++) acc[i][j] = 0.f;
    #pragma unroll
    for (int j = 0; j < 4; j++) lacc[j] = 0.f;
    float mr0 = -1e30f, mr1 = -1e30f;
    const uint32_t ones2[2] = {0x3C003C00u, 0x3C003C00u};

    const int NT = SEQ / 64;
    for (int it = 0; it < NT; it++) {
        const int buf = it & 1;
        if (it + 1 < NT) { stageKV(it + 1, buf ^ 1); cp_commit(); cp_wait1(); }
        else             { cp_wait0(); }
        __syncthreads();

        if (it == 0) {
            #pragma unroll
            for (int ks = 0; ks < 4; ks++) {
                uint32_t off = (uint32_t)((w * 16 + frow) * QSTR + ks * 16 + fcol) * 2;
                ldsm4(sb + SM_QH + off, qh[ks]);
                ldsm4(sb + SM_QL + off, ql[ks]);
            }
        }

        // ---- S = Q K^T (3-pass bf16) ----
        float sC[8][4];
        #pragma unroll
        for (int i = 0; i < 8; i++)
            #pragma unroll
            for (int j = 0; j < 4; j++) sC[i][j] = 0.f;

        const uint32_t kbase = sb + SM_K + (uint32_t)buf * 18432;
        #pragma unroll
        for (int ks = 0; ks < 4; ks++) {
            uint32_t kb[8][2], klb[8][2];
            #pragma unroll
            for (int nfp = 0; nfp < 4; nfp++) {
                uint32_t off = (uint32_t)((nfp * 16 + kbrow) * QSTR + ks * 16 + kbcol) * 2;
                uint32_t r[4];
                ldsm4(kbase + off, r);
                kb[2*nfp][0] = r[0]; kb[2*nfp][1] = r[1];
                kb[2*nfp+1][0] = r[2]; kb[2*nfp+1][1] = r[3];
                ldsm4(kbase + 9216 + off, r);
                klb[2*nfp][0] = r[0]; klb[2*nfp][1] = r[1];
                klb[2*nfp+1][0] = r[2]; klb[2*nfp+1][1] = r[3];
            }
            #pragma unroll
            for (int nt = 0; nt < 8; nt++) mma16816(sC[nt], qh[ks], kb[nt]);
            #pragma unroll
            for (int nt = 0; nt < 8; nt++) mma16816(sC[nt], qh[ks], klb[nt]);
            #pragma unroll
            for (int nt = 0; nt < 8; nt++) mma16816(sC[nt], ql[ks], kb[nt]);
        }

        // ---- online softmax (raw-score units, scale folded into CEXP) ----
        float m0 = -1e30f, m1 = -1e30f;
        #pragma unroll
        for (int nt = 0; nt < 8; nt++) {
            m0 = fmaxf(m0, fmaxf(sC[nt][0], sC[nt][1]));
            m1 = fmaxf(m1, fmaxf(sC[nt][2], sC[nt][3]));
        }
        m0 = fmaxf(m0, __shfl_xor_sync(0xffffffffu, m0, 1));
        m0 = fmaxf(m0, __shfl_xor_sync(0xffffffffu, m0, 2));
        m1 = fmaxf(m1, __shfl_xor_sync(0xffffffffu, m1, 1));
        m1 = fmaxf(m1, __shfl_xor_sync(0xffffffffu, m1, 2));
        const float mn0 = fmaxf(mr0, m0), mn1 = fmaxf(mr1, m1);
        const float al0 = ex2f((mr0 - mn0) * CEXP);
        const float al1 = ex2f((mr1 - mn1) * CEXP);
        mr0 = mn0; mr1 = mn1;
        if (__any_sync(0xffffffffu, (al0 < 1.f) || (al1 < 1.f))) {
            #pragma unroll
            for (int nt = 0; nt < 8; nt++) {
                acc[nt][0] *= al0; acc[nt][1] *= al0;
                acc[nt][2] *= al1; acc[nt][3] *= al1;
            }
            lacc[0] *= al0; lacc[1] *= al0; lacc[2] *= al1; lacc[3] *= al1;
        }

        uint32_t pf[8][2];
        #pragma unroll
        for (int nt = 0; nt < 8; nt++) {
            pf[nt][0] = packex2((sC[nt][1] - mn0) * CEXP, (sC[nt][0] - mn0) * CEXP);
            pf[nt][1] = packex2((sC[nt][3] - mn1) * CEXP, (sC[nt][2] - mn1) * CEXP);
        }

        // ---- O += P V ; l += P·1 ----
        const uint32_t vbase = sb + SM_V + (uint32_t)buf * 9216;
        #pragma unroll
        for (int kt = 0; kt < 4; kt++) {
            uint32_t a[4] = {pf[2*kt][0], pf[2*kt][1], pf[2*kt+1][0], pf[2*kt+1][1]};
            #pragma unroll
            for (int nv = 0; nv < 4; nv++) {
                uint32_t off = (uint32_t)((kt * 16 + frow) * QSTR + nv * 16 + fcol) * 2;
                uint32_t r[4];
                ldsm4t(vbase + off, r);
                mma16816h(acc[2*nv],     a, r);
                mma16816h(acc[2*nv + 1], a, r + 2);
            }
            mma16816h(lacc, a, ones2);
        }
        __syncthreads();
    }

    // ---- normalize + store bf16 hi/lo ----
    const float il0 = 1.f / lacc[0];
    const float il1 = 1.f / lacc[2];
    const int r0 = rowbase + w * 16 + (lane >> 2);
    const int cb = h * HSZ + (lane & 3) * 2;
    #pragma unroll
    for (int nt = 0; nt < 8; nt++) {
        const int col = cb + nt * 8;
        float o0 = acc[nt][0] * il0, o1 = acc[nt][1] * il0;
        float o2 = acc[nt][2] * il1, o3 = acc[nt][3] * il1;
        __nv_bfloat16 h0 = __float2bfloat16(o0), h1 = __float2bfloat16(o1);
        __nv_bfloat16 h2 = __float2bfloat16(o2), h3 = __float2bfloat16(o3);
        __nv_bfloat162 hp0; hp0.x = h0; hp0.y = h1;
        __nv_bfloat162 hp1; hp1.x = h2; hp1.y = h3;
        __nv_bfloat162 lp0; lp0.x = __float2bfloat16(o0 - __bfloat162float(h0));
                            lp0.y = __float2bfloat16(o1 - __bfloat162float(h1));
        __nv_bfloat162 lp1; lp1.x = __float2bfloat16(o2 - __bfloat162float(h2));
                            lp1.y = __float2bfloat16(o3 - __bfloat162float(h3));
        *(__nv_bfloat162*)(Oh + (size_t)r0 * DIM + col)       = hp0;
        *(__nv_bfloat162*)(Ol + (size_t)r0 * DIM + col)       = lp0;
        *(__nv_bfloat162*)(Oh + (size_t)(r0 + 8) * DIM + col) = hp1;
        *(__nv_bfloat162*)(Ol + (size_t)(r0 + 8) * DIM + col) = lp1;
    }
}

// ============================ launch =========================================
extern "C" void kernel_launch(void* const* d_in, const int* in_sizes, int n_in,
                              void* d_out, int out_size)
{
    const float* x     = (const float*)d_in[0];
    const float* Wq    = (const float*)d_in[1];
    const float* Wk    = (const float*)d_in[2];
    const float* Wv    = (const float*)d_in[3];
    const float* Wo    = (const float*)d_in[4];
    const float* bo    = (const float*)d_in[5];
    const float* W1    = (const float*)d_in[6];
    const float* b1    = (const float*)d_in[7];
    const float* W2    = (const float*)d_in[8];
    const float* b2    = (const float*)d_in[9];
    const float* ln1_g = (const float*)d_in[10];
    const float* ln1_b = (const float*)d_in[11];
    const float* ln2_g = (const float*)d_in[12];
    const float* ln2_b = (const float*)d_in[13];
    float* out = (float*)d_out;

    float *px1;
    __half *pvf;
    __nv_bfloat16 *phh, *phl, *pqh, *pql, *pkh, *pkl, *patth, *pattl, *pffh, *pffl;
    __nv_bfloat16 *pwqh, *pwql, *pwkh, *pwkl, *pwvh, *pwvl;
    __nv_bfloat16 *pwoh, *pwol, *pw1h, *pw1l, *pw2h, *pw2l;
    cudaGetSymbolAddress((void**)&px1,  g_x1);
    cudaGetSymbolAddress((void**)&phh,  g_hh);
    cudaGetSymbolAddress((void**)&phl,  g_hl);
    cudaGetSymbolAddress((void**)&pqh,  g_qhh);
    cudaGetSymbolAddress((void**)&pql,  g_qll);
    cudaGetSymbolAddress((void**)&pkh,  g_khh);
    cudaGetSymbolAddress((void**)&pkl,  g_kll);
    cudaGetSymbolAddress((void**)&pvf,  g_vf);
    cudaGetSymbolAddress((void**)&patth, g_atth);
    cudaGetSymbolAddress((void**)&pattl, g_attl);
    cudaGetSymbolAddress((void**)&pffh, g_ffh);
    cudaGetSymbolAddress((void**)&pffl, g_ffl);
    cudaGetSymbolAddress((void**)&pwqh, g_wqh);
    cudaGetSymbolAddress((void**)&pwql, g_wql);
    cudaGetSymbolAddress((void**)&pwkh, g_wkh);
    cudaGetSymbolAddress((void**)&pwkl, g_wkl);
    cudaGetSymbolAddress((void**)&pwvh, g_wvh);
    cudaGetSymbolAddress((void**)&pwvl, g_wvl);
    cudaGetSymbolAddress((void**)&pwoh, g_woh);
    cudaGetSymbolAddress((void**)&pwol, g_wol);
    cudaGetSymbolAddress((void**)&pw1h, g_w1h);
    cudaGetSymbolAddress((void**)&pw1l, g_w1l);
    cudaGetSymbolAddress((void**)&pw2h, g_w2h);
    cudaGetSymbolAddress((void**)&pw2l, g_w2l);

    cudaFuncSetAttribute(attn_mma_kernel, cudaFuncAttributeMaxDynamicSharedMemorySize,
                         ATTN_SMEM_BYTES);
    cudaFuncSetAttribute(mma_gemm<1>, cudaFuncAttributeMaxDynamicSharedMemorySize,
                         GEMM_SMEM_BYTES);
    cudaFuncSetAttribute(mma_gemm<2>, cudaFuncAttributeMaxDynamicSharedMemorySize,
                         GEMM_SMEM_BYTES);
    cudaFuncSetAttribute(mma_gemm<3>, cudaFuncAttributeMaxDynamicSharedMemorySize,
                         GEMM_SMEM_BYTES);
    cudaFuncSetAttribute(mma_gemm<4>, cudaFuncAttributeMaxDynamicSharedMemorySize,
                         GEMM_SMEM_BYTES);

    // 0) weight transpose + hi/lo split
    wconv_kernel<1><<<dim3(DIM/32, DIM/32), 256>>>(Wq, pwqh, pwql, DIM, DIM);
    wconv_kernel<1><<<dim3(DIM/32, DIM/32), 256>>>(Wk, pwkh, pwkl, DIM, DIM);
    wconv_kernel<1><<<dim3(DIM/32, DIM/32), 256>>>(Wv, pwvh, pwvl, DIM, DIM);
    wconv_kernel<0><<<dim3(DIM/32, DIM/32), 256>>>(Wo, pwoh, pwol, DIM, DIM);
    wconv_kernel<0><<<dim3(DIM/32, FFDIM/32), 256>>>(W1, pw1h, pw1l, FFDIM, DIM);
    wconv_kernel<0><<<dim3(FFDIM/32, DIM/32), 256>>>(W2, pw2h, pw2l, DIM, FFDIM);

    // 1) h = LN1(x) -> bf16 hi/lo
    ln_kernel<<<ROWS, 256>>>(x, ln1_g, ln1_b, phh, phl);

    // 2) Q,K (bf16 hi/lo), V (fp16)
    dim3 gP(DIM / 128, ROWS / 128);
    mma_gemm<3><<<gP, 256, GEMM_SMEM_BYTES>>>(phh, phl, pwqh, pwql, nullptr, nullptr,
                                              nullptr, pqh, pql, nullptr, ROWS, DIM, DIM);
    mma_gemm<3><<<gP, 256, GEMM_SMEM_BYTES>>>(phh, phl, pwkh, pwkl, nullptr, nullptr,
                                              nullptr, pkh, pkl, nullptr, ROWS, DIM, DIM);
    mma_gemm<4><<<gP, 256, GEMM_SMEM_BYTES>>>(phh, phl, pwvh, pwvl, nullptr, nullptr,
                                              nullptr, nullptr, nullptr, pvf, ROWS, DIM, DIM);

    // 3) attention (tensor-core flash) -> bf16 hi/lo
    dim3 gAttn(SEQ / 128, HEADS, BATCH);
    attn_mma_kernel<<<gAttn, 256, ATTN_SMEM_BYTES>>>(pqh, pql, pkh, pkl, pvf, patth, pattl);

    // 4) x1 = x + attn @ Wo + bo (fp32)
    mma_gemm<2><<<gP, 256, GEMM_SMEM_BYTES>>>(patth, pattl, pwoh, pwol, bo, x,
                                              px1, nullptr, nullptr, nullptr, ROWS, DIM, DIM);

    // 5) h2 = LN2(x1) -> bf16 hi/lo
    ln_kernel<<<ROWS, 256>>>(px1, ln2_g, ln2_b, phh, phl);

    // 6) ff = relu(h2 @ W1 + b1) -> bf16 hi/lo
    dim3 gF(FFDIM / 128, ROWS / 128);
    mma_gemm<1><<<gF, 256, GEMM_SMEM_BYTES>>>(phh, phl, pw1h, pw1l, b1, nullptr,
                                              nullptr, pffh, pffl, nullptr, ROWS, FFDIM, DIM);

    // 7) out = x1 + ff @ W2 + b2 (fp32)
    mma_gemm<2><<<gP, 256, GEMM_SMEM_BYTES>>>(pffh, pffl, pw2h, pw2l, b2, px1,
                                              out, nullptr, nullptr, nullptr, ROWS, DIM, FFDIM);
}

// round 6
// speedup vs baseline: 3.5948x; 1.4587x over previous
#include <cuda_runtime.h>
#include <cuda_bf16.h>
#include <cuda_fp16.h>
#include <cstdint>
#include <cstddef>

// Problem constants
#define BATCH 2
#define SEQ   2048
#define DIM   1024
#define HEADS 16
#define HSZ   64
#define ROWS  (BATCH*SEQ)          // 4096
#define FFDIM (4*DIM)              // 4096
#define NQKV  (3*DIM)              // 3072

// ======================= PTX helpers (family-safe only) ======================
__device__ __forceinline__ uint32_t smem_to_u32(const void* smem_ptr) {
    uint32_t addr;
    asm("{ .reg .u64 tmp; cvta.to.shared.u64 tmp, %1; cvt.u32.u64 %0, tmp; }"
        : "=r"(addr) : "l"(smem_ptr));
    return addr;
}

__device__ __forceinline__ void cp16(uint32_t saddr, const void* gptr) {
    asm volatile("cp.async.cg.shared.global [%0], [%1], 16;"
                 :: "r"(saddr), "l"(gptr) : "memory");
}
__device__ __forceinline__ void cp_commit() {
    asm volatile("cp.async.commit_group;" ::: "memory");
}
__device__ __forceinline__ void cp_wait1() {
    asm volatile("cp.async.wait_group 1;" ::: "memory");
}
__device__ __forceinline__ void cp_wait0() {
    asm volatile("cp.async.wait_group 0;" ::: "memory");
}

__device__ __forceinline__ void ldsm4(uint32_t addr, uint32_t* r) {
    asm volatile("ldmatrix.sync.aligned.m8n8.x4.shared.b16 {%0,%1,%2,%3}, [%4];"
                 : "=r"(r[0]), "=r"(r[1]), "=r"(r[2]), "=r"(r[3]) : "r"(addr));
}
__device__ __forceinline__ void ldsm4t(uint32_t addr, uint32_t* r) {
    asm volatile("ldmatrix.sync.aligned.m8n8.x4.trans.shared.b16 {%0,%1,%2,%3}, [%4];"
                 : "=r"(r[0]), "=r"(r[1]), "=r"(r[2]), "=r"(r[3]) : "r"(addr));
}

__device__ __forceinline__ void mma16816h(float* c, const uint32_t* a, const uint32_t* b) {
    asm volatile(
        "mma.sync.aligned.m16n8k16.row.col.f32.f16.f16.f32 "
        "{%0,%1,%2,%3}, {%4,%5,%6,%7}, {%8,%9}, {%0,%1,%2,%3};"
        : "+f"(c[0]), "+f"(c[1]), "+f"(c[2]), "+f"(c[3])
        : "r"(a[0]), "r"(a[1]), "r"(a[2]), "r"(a[3]), "r"(b[0]), "r"(b[1]));
}

// pack two fp32 (hi goes to upper f16, lo to lower f16) then exp2 both halves
__device__ __forceinline__ uint32_t packex2(float hi, float lo) {
    uint32_t d;
    asm("cvt.rn.f16x2.f32 %0, %1, %2;" : "=r"(d) : "f"(hi), "f"(lo));
    asm("ex2.approx.f16x2 %0, %0;" : "+r"(d));
    return d;
}
__device__ __forceinline__ float ex2f(float x) {
    float r; asm("ex2.approx.ftz.f32 %0, %1;" : "=f"(r) : "f"(x)); return r;
}

// ---------------- scratch (static device arrays; no allocations) -------------
__device__ float g_x1 [ROWS * DIM];            // x + attn_out (fp32)

__device__ __half g_h  [ROWS * DIM];           // LN output (ln1 / ln2 reuse), fp16
__device__ __half g_q  [ROWS * DIM];
__device__ __half g_k  [ROWS * DIM];
__device__ __half g_v  [ROWS * DIM];
__device__ __half g_att[ROWS * DIM];
__device__ __half g_ff [ROWS * FFDIM];

// weights, transposed to [N, K] K-major, fp16 hi/lo split
__device__ __half g_wqkvh[NQKV * DIM], g_wqkvl[NQKV * DIM];   // Q rows 0-1023, K 1024-2047, V 2048-3071
__device__ __half g_woh[DIM * DIM],    g_wol[DIM * DIM];
__device__ __half g_w1h[FFDIM * DIM],  g_w1l[FFDIM * DIM];
__device__ __half g_w2h[DIM * FFDIM],  g_w2l[DIM * FFDIM];

// ==================== weight transpose + fp16 hi/lo split ====================
// Output Wt[Nout, Kout] K-major. MODE 0: in W[k*Nout + n] (row-major [K,N]).
// MODE 1: QKV layout, in W[(n>>6)*(DIM*HSZ) + k*HSZ + (n&63)], Kout==DIM.
template<int MODE>
__device__ __forceinline__ void wconv_body(const float* __restrict__ W,
                                           __half* __restrict__ Wh, __half* __restrict__ Wl,
                                           int Nout, int Kout, int noff)
{
    __shared__ float t[32][33];
    const int k0 = blockIdx.x * 32, n0 = blockIdx.y * 32;
    const int tx = threadIdx.x & 31, ty = threadIdx.x >> 5;  // 32 x 8
    #pragma unroll
    for (int j = 0; j < 4; j++) {
        int k = k0 + ty + j * 8;
        int n = n0 + tx;
        float v;
        if (MODE == 0) v = W[(size_t)k * Nout + n];
        else           v = W[(size_t)(n >> 6) * (DIM * HSZ) + (size_t)k * HSZ + (n & 63)];
        t[ty + j * 8][tx] = v;
    }
    __syncthreads();
    #pragma unroll
    for (int j = 0; j < 4; j++) {
        int n = n0 + ty + j * 8;
        int k = k0 + tx;
        float v = t[tx][ty + j * 8];
        __half h = __float2half_rn(v);
        Wh[(size_t)(noff + n) * Kout + k] = h;
        Wl[(size_t)(noff + n) * Kout + k] = __float2half_rn(v - __half2float(h));
    }
}

__global__ __launch_bounds__(256)
void wconv_qkv_kernel(const float* __restrict__ Wq, const float* __restrict__ Wk,
                      const float* __restrict__ Wv,
                      __half* __restrict__ Wh, __half* __restrict__ Wl)
{
    const int z = blockIdx.z;
    const float* W = (z == 0) ? Wq : (z == 1) ? Wk : Wv;
    wconv_body<1>(W, Wh, Wl, DIM, DIM, z * DIM);
}

template<int MODE>
__global__ __launch_bounds__(256)
void wconv_kernel(const float* __restrict__ W, __half* __restrict__ Wh,
                  __half* __restrict__ Wl, int Nout, int Kout)
{
    wconv_body<MODE>(W, Wh, Wl, Nout, Kout, 0);
}

// ============================ LayerNorm (fp16 out) ===========================
__global__ __launch_bounds__(256)
void ln_kernel(const float* __restrict__ x, const float* __restrict__ g,
               const float* __restrict__ b, __half* __restrict__ y)
{
    const int row = blockIdx.x;
    const int tid = threadIdx.x;
    const float* xr = x + (size_t)row * DIM;

    float4 v = *(const float4*)(xr + tid * 4);
    float s  = v.x + v.y + v.z + v.w;
    float ss = v.x*v.x + v.y*v.y + v.z*v.z + v.w*v.w;
    #pragma unroll
    for (int off = 16; off >= 1; off >>= 1) {
        s  += __shfl_xor_sync(0xffffffffu, s,  off);
        ss += __shfl_xor_sync(0xffffffffu, ss, off);
    }
    __shared__ float sbuf[8], ssbuf[8];
    const int w = tid >> 5, l = tid & 31;
    if (l == 0) { sbuf[w] = s; ssbuf[w] = ss; }
    __syncthreads();
    float st = 0.f, sst = 0.f;
    #pragma unroll
    for (int i = 0; i < 8; i++) { st += sbuf[i]; sst += ssbuf[i]; }
    const float mean = st * (1.0f / DIM);
    const float var  = sst * (1.0f / DIM) - mean * mean;
    const float rstd = rsqrtf(var + 1e-5f);

    float4 gg = *(const float4*)(g + tid * 4);
    float4 bb = *(const float4*)(b + tid * 4);
    float o0 = (v.x - mean) * rstd * gg.x + bb.x;
    float o1 = (v.y - mean) * rstd * gg.y + bb.y;
    float o2 = (v.z - mean) * rstd * gg.z + bb.z;
    float o3 = (v.w - mean) * rstd * gg.w + bb.w;

    size_t base = (size_t)row * DIM + tid * 4;
    *(__half2*)(y + base)     = __floats2half2_rn(o0, o1);
    *(__half2*)(y + base + 2) = __floats2half2_rn(o2, o3);
}

// ==================== fp16 2-pass mma.sync GEMM ==============================
// C[M,N] = A[M,K] @ Wt[N,K]^T,  A single fp16, Wt fp16 hi/lo, 2 passes.
// EPI: 0 = fp16 out routed to O0/O1/O2 by col>>10 (row stride DIM);
//      1 = relu(acc+bias) -> O0 fp16 (row stride N);
//      2 = acc+bias+res   -> Cf fp32.
#define BK 32
#define SSTRIDE 40
#define TILE_ELEMS (128 * SSTRIDE)            // 5120
#define TILE_BYTES (TILE_ELEMS * 2)           // 10240
#define STAGE_BYTES (3 * TILE_BYTES)          // 30720
#define GEMM_SMEM_BYTES (2 * STAGE_BYTES)     // 61440

template<int EPI>
__global__ __launch_bounds__(256)
void mma_gemm(const __half* __restrict__ A,
              const __half* __restrict__ Bh, const __half* __restrict__ Bl,
              const float* __restrict__ bias, const float* __restrict__ res,
              float* __restrict__ Cf,
              __half* __restrict__ O0, __half* __restrict__ O1, __half* __restrict__ O2,
              int M, int N, int K)
{
    extern __shared__ __align__(16) char sm_raw[];
    const uint32_t sbase = smem_to_u32(sm_raw);

    const int tid  = threadIdx.x;
    const int lane = tid & 31;
    const int wid  = tid >> 5;
    const int wr   = wid >> 2;
    const int wc   = wid & 3;
    const int m0 = blockIdx.y * 128;
    const int n0 = blockIdx.x * 128;

    const int lrow = tid >> 1;
    const int lkf  = (tid & 1) * 16;

    auto stage_load = [&](int c, int buf) {
        const int k0 = c * BK;
        const uint32_t s0 = sbase + (uint32_t)buf * STAGE_BYTES;
        const uint32_t soff = (uint32_t)(lrow * SSTRIDE + lkf) * 2;
        {
            const __half* gp = A + (size_t)(m0 + lrow) * K + k0 + lkf;
            cp16(s0 + soff, gp); cp16(s0 + soff + 16, gp + 8);
        }
        {
            const __half* gp = Bh + (size_t)(n0 + lrow) * K + k0 + lkf;
            cp16(s0 + TILE_BYTES + soff, gp); cp16(s0 + TILE_BYTES + soff + 16, gp + 8);
        }
        {
            const __half* gp = Bl + (size_t)(n0 + lrow) * K + k0 + lkf;
            cp16(s0 + 2*TILE_BYTES + soff, gp); cp16(s0 + 2*TILE_BYTES + soff + 16, gp + 8);
        }
        cp_commit();
    };

    float acc[16][4];
    #pragma unroll
    for (int i = 0; i < 16; i++)
        #pragma unroll
        for (int j = 0; j < 4; j++) acc[i][j] = 0.f;

    const int a_mr = wr * 64 + (lane & 7) + ((lane >> 3) & 1) * 8;
    const int a_kc = (lane >> 4) * 8;
    const int b_nr = wc * 32 + (lane & 7) + (lane >> 4) * 8;
    const int b_kc = ((lane >> 3) & 1) * 8;

    const int nc = K / BK;
    stage_load(0, 0);

    for (int c = 0; c < nc; c++) {
        if (c + 1 < nc) { stage_load(c + 1, (c + 1) & 1); cp_wait1(); }
        else            { cp_wait0(); }
        __syncthreads();

        const uint32_t aT = sbase + (uint32_t)(c & 1) * STAGE_BYTES;
        const uint32_t bH = aT + TILE_BYTES;
        const uint32_t bL = aT + 2 * TILE_BYTES;

        #pragma unroll
        for (int ks = 0; ks < 2; ks++) {
            uint32_t af[4][4], bh[4][2], bl[4][2];
            #pragma unroll
            for (int mf = 0; mf < 4; mf++) {
                uint32_t off = (uint32_t)((a_mr + mf * 16) * SSTRIDE + a_kc + ks * 16) * 2;
                ldsm4(aT + off, af[mf]);
            }
            #pragma unroll
            for (int nfp = 0; nfp < 2; nfp++) {
                uint32_t off = (uint32_t)((b_nr + nfp * 16) * SSTRIDE + b_kc + ks * 16) * 2;
                uint32_t r[4];
                ldsm4(bH + off, r);
                bh[2*nfp][0] = r[0]; bh[2*nfp][1] = r[1];
                bh[2*nfp+1][0] = r[2]; bh[2*nfp+1][1] = r[3];
                ldsm4(bL + off, r);
                bl[2*nfp][0] = r[0]; bl[2*nfp][1] = r[1];
                bl[2*nfp+1][0] = r[2]; bl[2*nfp+1][1] = r[3];
            }
            #pragma unroll
            for (int mf = 0; mf < 4; mf++)
                #pragma unroll
                for (int nf = 0; nf < 4; nf++)
                    mma16816h(acc[mf*4+nf], af[mf], bh[nf]);
            #pragma unroll
            for (int mf = 0; mf < 4; mf++)
                #pragma unroll
                for (int nf = 0; nf < 4; nf++)
                    mma16816h(acc[mf*4+nf], af[mf], bl[nf]);
        }
        __syncthreads();
    }

    // ---------------- epilogue ----------------
    const int lr = lane >> 2;
    const int lc = (lane & 3) * 2;
    #pragma unroll
    for (int mf = 0; mf < 4; mf++) {
        #pragma unroll
        for (int nf = 0; nf < 4; nf++) {
            const int row = m0 + wr * 64 + mf * 16 + lr;
            const int col = n0 + wc * 32 + nf * 8 + lc;
            const float* cc = acc[mf*4+nf];
            if (EPI == 0) {
                const int which = col >> 10;
                const int c = col & (DIM - 1);
                __half* Op = (which == 0) ? O0 : (which == 1) ? O1 : O2;
                *(__half2*)(Op + (size_t)row * DIM + c)       = __floats2half2_rn(cc[0], cc[1]);
                *(__half2*)(Op + (size_t)(row + 8) * DIM + c) = __floats2half2_rn(cc[2], cc[3]);
            } else if (EPI == 1) {
                float2 bb = *(const float2*)(bias + col);
                float v0 = fmaxf(cc[0] + bb.x, 0.f), v1 = fmaxf(cc[1] + bb.y, 0.f);
                float v2 = fmaxf(cc[2] + bb.x, 0.f), v3 = fmaxf(cc[3] + bb.y, 0.f);
                *(__half2*)(O0 + (size_t)row * N + col)       = __floats2half2_rn(v0, v1);
                *(__half2*)(O0 + (size_t)(row + 8) * N + col) = __floats2half2_rn(v2, v3);
            } else {
                float2 bb = *(const float2*)(bias + col);
                float2 r0 = *(const float2*)(res + (size_t)row * N + col);
                float2 r1 = *(const float2*)(res + (size_t)(row + 8) * N + col);
                float2 v0 = make_float2(cc[0] + bb.x + r0.x, cc[1] + bb.y + r0.y);
                float2 v1 = make_float2(cc[2] + bb.x + r1.x, cc[3] + bb.y + r1.y);
                *(float2*)(Cf + (size_t)row * N + col)       = v0;
                *(float2*)(Cf + (size_t)(row + 8) * N + col) = v1;
            }
        }
    }
}

// ==================== mma flash attention (fp16, 1-pass S) ===================
// grid (SEQ/128, HEADS, BATCH), 256 threads (8 warps, warp w owns rows w*16..+15).
#define QSTR 72
#define SM_Q  0
#define SM_K  (128*QSTR*2)                    // 18432 ; 2 bufs x 9216
#define SM_V  (SM_K + 2*9216)                 // 36864 ; 2 bufs x 9216
#define ATTN_SMEM_BYTES (SM_V + 2*9216)       // 55296
#define CEXP 0.1803368801111f                 // log2(e)/8

__global__ __launch_bounds__(256)
void attn_mma_kernel(const __half* __restrict__ Q_, const __half* __restrict__ K_,
                     const __half* __restrict__ V_, __half* __restrict__ O)
{
    extern __shared__ __align__(16) char smraw[];
    const uint32_t sb = smem_to_u32(smraw);
    const int tid = threadIdx.x, lane = tid & 31, w = tid >> 5;
    const int h = blockIdx.y, bz = blockIdx.z;
    const int rowbase = bz * SEQ + blockIdx.x * 128;
    const size_t gQrow0 = (size_t)rowbase * DIM + h * HSZ;
    const size_t gKbase = (size_t)bz * SEQ * DIM + h * HSZ;

    // ---- stage Q ----
    {
        int r = tid >> 1, cc = (tid & 1) * 4;
        const char* gq = (const char*)(Q_ + gQrow0 + (size_t)r * DIM);
        uint32_t sq = sb + SM_Q + (uint32_t)(r * QSTR) * 2;
        #pragma unroll
        for (int i = 0; i < 4; i++)
            cp16(sq + (cc + i) * 16, gq + (cc + i) * 16);
    }
    auto stageKV = [&](int it, int buf) {
        int r = tid >> 2, c0 = (tid & 3) * 32;
        size_t grow = gKbase + (size_t)(it * 64 + r) * DIM;
        uint32_t kk = sb + SM_K + (uint32_t)buf * 9216 + (uint32_t)(r * QSTR) * 2;
        uint32_t vv = sb + SM_V + (uint32_t)buf * 9216 + (uint32_t)(r * QSTR) * 2;
        cp16(kk + c0,      (const char*)(K_ + grow) + c0);
        cp16(kk + c0 + 16, (const char*)(K_ + grow) + c0 + 16);
        cp16(vv + c0,      (const char*)(V_ + grow) + c0);
        cp16(vv + c0 + 16, (const char*)(V_ + grow) + c0 + 16);
    };
    stageKV(0, 0);
    cp_commit();

    // A-operand lane pattern (Q, and V-trans)
    const int frow = (lane & 7) + ((lane >> 3) & 1) * 8;
    const int fcol = (lane >> 4) * 8;
    // B-operand lane pattern (K, non-trans)
    const int kbrow = (lane & 7) + (lane >> 4) * 8;
    const int kbcol = ((lane >> 3) & 1) * 8;

    uint32_t qf[4][4];
    float acc[8][4], lacc[4];
    #pragma unroll
    for (int i = 0; i < 8; i++)
        #pragma unroll
        for (int j = 0; j < 4; j++) acc[i][j] = 0.f;
    #pragma unroll
    for (int j = 0; j < 4; j++) lacc[j] = 0.f;
    float mr0 = -1e30f, mr1 = -1e30f;
    const uint32_t ones2[2] = {0x3C003C00u, 0x3C003C00u};

    const int NT = SEQ / 64;
    for (int it = 0; it < NT; it++) {
        const int buf = it & 1;
        if (it + 1 < NT) { stageKV(it + 1, buf ^ 1); cp_commit(); cp_wait1(); }
        else             { cp_wait0(); }
        __syncthreads();

        if (it == 0) {
            #pragma unroll
            for (int ks = 0; ks < 4; ks++) {
                uint32_t off = (uint32_t)((w * 16 + frow) * QSTR + ks * 16 + fcol) * 2;
                ldsm4(sb + SM_Q + off, qf[ks]);
            }
        }

        // ---- S = Q K^T (single-pass fp16) ----
        float sC[8][4];
        #pragma unroll
        for (int i = 0; i < 8; i++)
            #pragma unroll
            for (int j = 0; j < 4; j++) sC[i][j] = 0.f;

        const uint32_t kbase = sb + SM_K + (uint32_t)buf * 9216;
        #pragma unroll
        for (int ks = 0; ks < 4; ks++) {
            uint32_t kb[8][2];
            #pragma unroll
            for (int nfp = 0; nfp < 4; nfp++) {
                uint32_t off = (uint32_t)((nfp * 16 + kbrow) * QSTR + ks * 16 + kbcol) * 2;
                uint32_t r[4];
                ldsm4(kbase + off, r);
                kb[2*nfp][0] = r[0]; kb[2*nfp][1] = r[1];
                kb[2*nfp+1][0] = r[2]; kb[2*nfp+1][1] = r[3];
            }
            #pragma unroll
            for (int nt = 0; nt < 8; nt++) mma16816h(sC[nt], qf[ks], kb[nt]);
        }

        // ---- online softmax (raw-score units, scale folded into CEXP) ----
        float m0 = -1e30f, m1 = -1e30f;
        #pragma unroll
        for (int nt = 0; nt < 8; nt++) {
            m0 = fmaxf(m0, fmaxf(sC[nt][0], sC[nt][1]));
            m1 = fmaxf(m1, fmaxf(sC[nt][2], sC[nt][3]));
        }
        m0 = fmaxf(m0, __shfl_xor_sync(0xffffffffu, m0, 1));
        m0 = fmaxf(m0, __shfl_xor_sync(0xffffffffu, m0, 2));
        m1 = fmaxf(m1, __shfl_xor_sync(0xffffffffu, m1, 1));
        m1 = fmaxf(m1, __shfl_xor_sync(0xffffffffu, m1, 2));
        const float mn0 = fmaxf(mr0, m0), mn1 = fmaxf(mr1, m1);
        const float al0 = ex2f((mr0 - mn0) * CEXP);
        const float al1 = ex2f((mr1 - mn1) * CEXP);
        mr0 = mn0; mr1 = mn1;
        if (__any_sync(0xffffffffu, (al0 < 1.f) || (al1 < 1.f))) {
            #pragma unroll
            for (int nt = 0; nt < 8; nt++) {
                acc[nt][0] *= al0; acc[nt][1] *= al0;
                acc[nt][2] *= al1; acc[nt][3] *= al1;
            }
            lacc[0] *= al0; lacc[1] *= al0; lacc[2] *= al1; lacc[3] *= al1;
        }

        uint32_t pf[8][2];
        #pragma unroll
        for (int nt = 0; nt < 8; nt++) {
            pf[nt][0] = packex2((sC[nt][1] - mn0) * CEXP, (sC[nt][0] - mn0) * CEXP);
            pf[nt][1] = packex2((sC[nt][3] - mn1) * CEXP, (sC[nt][2] - mn1) * CEXP);
        }

        // ---- O += P V ; l += P·1 ----
        const uint32_t vbase = sb + SM_V + (uint32_t)buf * 9216;
        #pragma unroll
        for (int kt = 0; kt < 4; kt++) {
            uint32_t a[4] = {pf[2*kt][0], pf[2*kt][1], pf[2*kt+1][0], pf[2*kt+1][1]};
            #pragma unroll
            for (int nv = 0; nv < 4; nv++) {
                uint32_t off = (uint32_t)((kt * 16 + frow) * QSTR + nv * 16 + fcol) * 2;
                uint32_t r[4];
                ldsm4t(vbase + off, r);
                mma16816h(acc[2*nv],     a, r);
                mma16816h(acc[2*nv + 1], a, r + 2);
            }
            mma16816h(lacc, a, ones2);
        }
        __syncthreads();
    }

    // ---- normalize + store fp16 ----
    const float il0 = 1.f / lacc[0];
    const float il1 = 1.f / lacc[2];
    const int r0 = rowbase + w * 16 + (lane >> 2);
    const int cb = h * HSZ + (lane & 3) * 2;
    #pragma unroll
    for (int nt = 0; nt < 8; nt++) {
        const int col = cb + nt * 8;
        *(__half2*)(O + (size_t)r0 * DIM + col) =
            __floats2half2_rn(acc[nt][0] * il0, acc[nt][1] * il0);
        *(__half2*)(O + (size_t)(r0 + 8) * DIM + col) =
            __floats2half2_rn(acc[nt][2] * il1, acc[nt][3] * il1);
    }
}

// ============================ launch =========================================
extern "C" void kernel_launch(void* const* d_in, const int* in_sizes, int n_in,
                              void* d_out, int out_size)
{
    const float* x     = (const float*)d_in[0];
    const float* Wq    = (const float*)d_in[1];
    const float* Wk    = (const float*)d_in[2];
    const float* Wv    = (const float*)d_in[3];
    const float* Wo    = (const float*)d_in[4];
    const float* bo    = (const float*)d_in[5];
    const float* W1    = (const float*)d_in[6];
    const float* b1    = (const float*)d_in[7];
    const float* W2    = (const float*)d_in[8];
    const float* b2    = (const float*)d_in[9];
    const float* ln1_g = (const float*)d_in[10];
    const float* ln1_b = (const float*)d_in[11];
    const float* ln2_g = (const float*)d_in[12];
    const float* ln2_b = (const float*)d_in[13];
    float* out = (float*)d_out;

    float *px1;
    __half *ph, *pq, *pk, *pv, *patt, *pff;
    __half *pwqkvh, *pwqkvl, *pwoh, *pwol, *pw1h, *pw1l, *pw2h, *pw2l;
    cudaGetSymbolAddress((void**)&px1, g_x1);
    cudaGetSymbolAddress((void**)&ph,  g_h);
    cudaGetSymbolAddress((void**)&pq,  g_q);
    cudaGetSymbolAddress((void**)&pk,  g_k);
    cudaGetSymbolAddress((void**)&pv,  g_v);
    cudaGetSymbolAddress((void**)&patt, g_att);
    cudaGetSymbolAddress((void**)&pff, g_ff);
    cudaGetSymbolAddress((void**)&pwqkvh, g_wqkvh);
    cudaGetSymbolAddress((void**)&pwqkvl, g_wqkvl);
    cudaGetSymbolAddress((void**)&pwoh, g_woh);
    cudaGetSymbolAddress((void**)&pwol, g_wol);
    cudaGetSymbolAddress((void**)&pw1h, g_w1h);
    cudaGetSymbolAddress((void**)&pw1l, g_w1l);
    cudaGetSymbolAddress((void**)&pw2h, g_w2h);
    cudaGetSymbolAddress((void**)&pw2l, g_w2l);

    cudaFuncSetAttribute(attn_mma_kernel, cudaFuncAttributeMaxDynamicSharedMemorySize,
                         ATTN_SMEM_BYTES);
    cudaFuncSetAttribute(mma_gemm<0>, cudaFuncAttributeMaxDynamicSharedMemorySize,
                         GEMM_SMEM_BYTES);
    cudaFuncSetAttribute(mma_gemm<1>, cudaFuncAttributeMaxDynamicSharedMemorySize,
                         GEMM_SMEM_BYTES);
    cudaFuncSetAttribute(mma_gemm<2>, cudaFuncAttributeMaxDynamicSharedMemorySize,
                         GEMM_SMEM_BYTES);

    // 0) weight transpose + fp16 hi/lo split   (launches 0..3)
    wconv_qkv_kernel<<<dim3(DIM/32, DIM/32, 3), 256>>>(Wq, Wk, Wv, pwqkvh, pwqkvl);
    wconv_kernel<0><<<dim3(DIM/32, DIM/32), 256>>>(Wo, pwoh, pwol, DIM, DIM);
    wconv_kernel<0><<<dim3(DIM/32, FFDIM/32), 256>>>(W1, pw1h, pw1l, FFDIM, DIM);
    wconv_kernel<0><<<dim3(FFDIM/32, DIM/32), 256>>>(W2, pw2h, pw2l, DIM, FFDIM);

    // 1) h = LN1(x) -> fp16                    (launch 4)
    ln_kernel<<<ROWS, 256>>>(x, ln1_g, ln1_b, ph);

    // 2) fused QKV projection -> fp16          (launch 5 <- ncu capture)
    dim3 gQKV(NQKV / 128, ROWS / 128);           // (24, 32)
    mma_gemm<0><<<gQKV, 256, GEMM_SMEM_BYTES>>>(ph, pwqkvh, pwqkvl, nullptr, nullptr,
                                                nullptr, pq, pk, pv, ROWS, NQKV, DIM);

    // 3) attention (fp16 tensor-core flash) -> fp16
    dim3 gAttn(SEQ / 128, HEADS, BATCH);
    attn_mma_kernel<<<gAttn, 256, ATTN_SMEM_BYTES>>>(pq, pk, pv, patt);

    // 4) x1 = x + attn @ Wo + bo (fp32)
    dim3 gP(DIM / 128, ROWS / 128);              // (8, 32)
    mma_gemm<2><<<gP, 256, GEMM_SMEM_BYTES>>>(patt, pwoh, pwol, bo, x,
                                              px1, nullptr, nullptr, nullptr, ROWS, DIM, DIM);

    // 5) h2 = LN2(x1) -> fp16
    ln_kernel<<<ROWS, 256>>>(px1, ln2_g, ln2_b, ph);

    // 6) ff = relu(h2 @ W1 + b1) -> fp16
    dim3 gF(FFDIM / 128, ROWS / 128);            // (32, 32)
    mma_gemm<1><<<gF, 256, GEMM_SMEM_BYTES>>>(ph, pw1h, pw1l, b1, nullptr,
                                              nullptr, pff, nullptr, nullptr, ROWS, FFDIM, DIM);

    // 7) out = x1 + ff @ W2 + b2 (fp32)
    mma_gemm<2><<<gP, 256, GEMM_SMEM_BYTES>>>(pff, pw2h, pw2l, b2, px1,
                                              out, nullptr, nullptr, nullptr, ROWS, DIM, FFDIM);
}

// round 7
// speedup vs baseline: 5.1931x; 1.4446x over previous
#include <cuda_runtime.h>
#include <cuda_bf16.h>
#include <cuda_fp16.h>
#include <cstdint>
#include <cstddef>

// Problem constants
#define BATCH 2
#define SEQ   2048
#define DIM   1024
#define HEADS 16
#define HSZ   64
#define ROWS  (BATCH*SEQ)          // 4096
#define FFDIM (4*DIM)              // 4096
#define NQKV  (3*DIM)              // 3072

// ======================= PTX helpers (family-safe only) ======================
__device__ __forceinline__ uint32_t smem_to_u32(const void* smem_ptr) {
    uint32_t addr;
    asm("{ .reg .u64 tmp; cvta.to.shared.u64 tmp, %1; cvt.u32.u64 %0, tmp; }"
        : "=r"(addr) : "l"(smem_ptr));
    return addr;
}

__device__ __forceinline__ void cp16(uint32_t saddr, const void* gptr) {
    asm volatile("cp.async.cg.shared.global [%0], [%1], 16;"
                 :: "r"(saddr), "l"(gptr) : "memory");
}
__device__ __forceinline__ void cp_commit() {
    asm volatile("cp.async.commit_group;" ::: "memory");
}
__device__ __forceinline__ void cp_wait1() {
    asm volatile("cp.async.wait_group 1;" ::: "memory");
}
__device__ __forceinline__ void cp_wait0() {
    asm volatile("cp.async.wait_group 0;" ::: "memory");
}

__device__ __forceinline__ void ldsm4(uint32_t addr, uint32_t* r) {
    asm volatile("ldmatrix.sync.aligned.m8n8.x4.shared.b16 {%0,%1,%2,%3}, [%4];"
                 : "=r"(r[0]), "=r"(r[1]), "=r"(r[2]), "=r"(r[3]) : "r"(addr));
}
__device__ __forceinline__ void ldsm4t(uint32_t addr, uint32_t* r) {
    asm volatile("ldmatrix.sync.aligned.m8n8.x4.trans.shared.b16 {%0,%1,%2,%3}, [%4];"
                 : "=r"(r[0]), "=r"(r[1]), "=r"(r[2]), "=r"(r[3]) : "r"(addr));
}

__device__ __forceinline__ void mma16816h(float* c, const uint32_t* a, const uint32_t* b) {
    asm volatile(
        "mma.sync.aligned.m16n8k16.row.col.f32.f16.f16.f32 "
        "{%0,%1,%2,%3}, {%4,%5,%6,%7}, {%8,%9}, {%0,%1,%2,%3};"
        : "+f"(c[0]), "+f"(c[1]), "+f"(c[2]), "+f"(c[3])
        : "r"(a[0]), "r"(a[1]), "r"(a[2]), "r"(a[3]), "r"(b[0]), "r"(b[1]));
}

// pack two fp32 (hi goes to upper f16, lo to lower f16) then exp2 both halves
__device__ __forceinline__ uint32_t packex2(float hi, float lo) {
    uint32_t d;
    asm("cvt.rn.f16x2.f32 %0, %1, %2;" : "=r"(d) : "f"(hi), "f"(lo));
    asm("ex2.approx.f16x2 %0, %0;" : "+r"(d));
    return d;
}
__device__ __forceinline__ float ex2f(float x) {
    float r; asm("ex2.approx.ftz.f32 %0, %1;" : "=f"(r) : "f"(x)); return r;
}

// ---------------- scratch (static device arrays; no allocations) -------------
__device__ float g_x1 [ROWS * DIM];            // x + attn_out (fp32)

__device__ __half g_h  [ROWS * DIM];           // LN output (ln1 / ln2 reuse), fp16
__device__ __half g_q  [ROWS * DIM];
__device__ __half g_k  [ROWS * DIM];
__device__ __half g_v  [ROWS * DIM];
__device__ __half g_att[ROWS * DIM];
__device__ __half g_ff [ROWS * FFDIM];

// weights, transposed to [N, K] K-major, single fp16
__device__ __half g_wqkv[NQKV * DIM];          // Q rows 0-1023, K 1024-2047, V 2048-3071
__device__ __half g_wo  [DIM * DIM];
__device__ __half g_w1  [FFDIM * DIM];
__device__ __half g_w2  [DIM * FFDIM];

// ==================== weight transpose + fp16 convert ========================
// Output Wt[Nout, Kout] K-major. MODE 0: in W[k*Nout + n] (row-major [K,N]).
// MODE 1: QKV layout, in W[(n>>6)*(DIM*HSZ) + k*HSZ + (n&63)], Kout==DIM.
template<int MODE>
__device__ __forceinline__ void wconv_body(const float* __restrict__ W,
                                           __half* __restrict__ Wh,
                                           int Nout, int Kout, int noff)
{
    __shared__ float t[32][33];
    const int k0 = blockIdx.x * 32, n0 = blockIdx.y * 32;
    const int tx = threadIdx.x & 31, ty = threadIdx.x >> 5;  // 32 x 8
    #pragma unroll
    for (int j = 0; j < 4; j++) {
        int k = k0 + ty + j * 8;
        int n = n0 + tx;
        float v;
        if (MODE == 0) v = W[(size_t)k * Nout + n];
        else           v = W[(size_t)(n >> 6) * (DIM * HSZ) + (size_t)k * HSZ + (n & 63)];
        t[ty + j * 8][tx] = v;
    }
    __syncthreads();
    #pragma unroll
    for (int j = 0; j < 4; j++) {
        int n = n0 + ty + j * 8;
        int k = k0 + tx;
        Wh[(size_t)(noff + n) * Kout + k] = __float2half_rn(t[tx][ty + j * 8]);
    }
}

__global__ __launch_bounds__(256)
void wconv_qkv_kernel(const float* __restrict__ Wq, const float* __restrict__ Wk,
                      const float* __restrict__ Wv, __half* __restrict__ Wh)
{
    const int z = blockIdx.z;
    const float* W = (z == 0) ? Wq : (z == 1) ? Wk : Wv;
    wconv_body<1>(W, Wh, DIM, DIM, z * DIM);
}

template<int MODE>
__global__ __launch_bounds__(256)
void wconv_kernel(const float* __restrict__ W, __half* __restrict__ Wh,
                  int Nout, int Kout)
{
    wconv_body<MODE>(W, Wh, Nout, Kout, 0);
}

// ============================ LayerNorm (fp16 out) ===========================
__global__ __launch_bounds__(256)
void ln_kernel(const float* __restrict__ x, const float* __restrict__ g,
               const float* __restrict__ b, __half* __restrict__ y)
{
    const int row = blockIdx.x;
    const int tid = threadIdx.x;
    const float* xr = x + (size_t)row * DIM;

    float4 v = *(const float4*)(xr + tid * 4);
    float s  = v.x + v.y + v.z + v.w;
    float ss = v.x*v.x + v.y*v.y + v.z*v.z + v.w*v.w;
    #pragma unroll
    for (int off = 16; off >= 1; off >>= 1) {
        s  += __shfl_xor_sync(0xffffffffu, s,  off);
        ss += __shfl_xor_sync(0xffffffffu, ss, off);
    }
    __shared__ float sbuf[8], ssbuf[8];
    const int w = tid >> 5, l = tid & 31;
    if (l == 0) { sbuf[w] = s; ssbuf[w] = ss; }
    __syncthreads();
    float st = 0.f, sst = 0.f;
    #pragma unroll
    for (int i = 0; i < 8; i++) { st += sbuf[i]; sst += ssbuf[i]; }
    const float mean = st * (1.0f / DIM);
    const float var  = sst * (1.0f / DIM) - mean * mean;
    const float rstd = rsqrtf(var + 1e-5f);

    float4 gg = *(const float4*)(g + tid * 4);
    float4 bb = *(const float4*)(b + tid * 4);
    float o0 = (v.x - mean) * rstd * gg.x + bb.x;
    float o1 = (v.y - mean) * rstd * gg.y + bb.y;
    float o2 = (v.z - mean) * rstd * gg.z + bb.z;
    float o3 = (v.w - mean) * rstd * gg.w + bb.w;

    size_t base = (size_t)row * DIM + tid * 4;
    *(__half2*)(y + base)     = __floats2half2_rn(o0, o1);
    *(__half2*)(y + base + 2) = __floats2half2_rn(o2, o3);
}

// ==================== fp16 single-pass mma.sync GEMM =========================
// C[M,N] = A[M,K] @ Wt[N,K]^T,  A and Wt single fp16.
// EPI: 0 = fp16 out routed to O0/O1/O2 by col>>10 (row stride DIM);
//      1 = relu(acc+bias) -> O0 fp16 (row stride N);
//      2 = acc+bias+res   -> Cf fp32.
#define BK 32
#define SSTRIDE 40
#define TILE_ELEMS (128 * SSTRIDE)            // 5120
#define TILE_BYTES (TILE_ELEMS * 2)           // 10240
#define STAGE_BYTES (2 * TILE_BYTES)          // 20480
#define GEMM_SMEM_BYTES (2 * STAGE_BYTES)     // 40960

template<int EPI>
__global__ __launch_bounds__(256, 2)
void mma_gemm(const __half* __restrict__ A, const __half* __restrict__ B,
              const float* __restrict__ bias, const float* __restrict__ res,
              float* __restrict__ Cf,
              __half* __restrict__ O0, __half* __restrict__ O1, __half* __restrict__ O2,
              int M, int N, int K)
{
    extern __shared__ __align__(16) char sm_raw[];
    const uint32_t sbase = smem_to_u32(sm_raw);

    const int tid  = threadIdx.x;
    const int lane = tid & 31;
    const int wid  = tid >> 5;
    const int wr   = wid >> 2;
    const int wc   = wid & 3;
    const int m0 = blockIdx.y * 128;
    const int n0 = blockIdx.x * 128;

    const int lrow = tid >> 1;
    const int lkf  = (tid & 1) * 16;

    auto stage_load = [&](int c, int buf) {
        const int k0 = c * BK;
        const uint32_t s0 = sbase + (uint32_t)buf * STAGE_BYTES;
        const uint32_t soff = (uint32_t)(lrow * SSTRIDE + lkf) * 2;
        {
            const __half* gp = A + (size_t)(m0 + lrow) * K + k0 + lkf;
            cp16(s0 + soff, gp); cp16(s0 + soff + 16, gp + 8);
        }
        {
            const __half* gp = B + (size_t)(n0 + lrow) * K + k0 + lkf;
            cp16(s0 + TILE_BYTES + soff, gp); cp16(s0 + TILE_BYTES + soff + 16, gp + 8);
        }
        cp_commit();
    };

    float acc[16][4];
    #pragma unroll
    for (int i = 0; i < 16; i++)
        #pragma unroll
        for (int j = 0; j < 4; j++) acc[i][j] = 0.f;

    const int a_mr = wr * 64 + (lane & 7) + ((lane >> 3) & 1) * 8;
    const int a_kc = (lane >> 4) * 8;
    const int b_nr = wc * 32 + (lane & 7) + (lane >> 4) * 8;
    const int b_kc = ((lane >> 3) & 1) * 8;

    const int nc = K / BK;
    stage_load(0, 0);

    for (int c = 0; c < nc; c++) {
        if (c + 1 < nc) { stage_load(c + 1, (c + 1) & 1); cp_wait1(); }
        else            { cp_wait0(); }
        __syncthreads();

        const uint32_t aT = sbase + (uint32_t)(c & 1) * STAGE_BYTES;
        const uint32_t bT = aT + TILE_BYTES;

        #pragma unroll
        for (int ks = 0; ks < 2; ks++) {
            uint32_t af[4][4], bf[4][2];
            #pragma unroll
            for (int mf = 0; mf < 4; mf++) {
                uint32_t off = (uint32_t)((a_mr + mf * 16) * SSTRIDE + a_kc + ks * 16) * 2;
                ldsm4(aT + off, af[mf]);
            }
            #pragma unroll
            for (int nfp = 0; nfp < 2; nfp++) {
                uint32_t off = (uint32_t)((b_nr + nfp * 16) * SSTRIDE + b_kc + ks * 16) * 2;
                uint32_t r[4];
                ldsm4(bT + off, r);
                bf[2*nfp][0] = r[0]; bf[2*nfp][1] = r[1];
                bf[2*nfp+1][0] = r[2]; bf[2*nfp+1][1] = r[3];
            }
            #pragma unroll
            for (int mf = 0; mf < 4; mf++)
                #pragma unroll
                for (int nf = 0; nf < 4; nf++)
                    mma16816h(acc[mf*4+nf], af[mf], bf[nf]);
        }
        __syncthreads();
    }

    // ---------------- epilogue ----------------
    const int lr = lane >> 2;
    const int lc = (lane & 3) * 2;
    #pragma unroll
    for (int mf = 0; mf < 4; mf++) {
        #pragma unroll
        for (int nf = 0; nf < 4; nf++) {
            const int row = m0 + wr * 64 + mf * 16 + lr;
            const int col = n0 + wc * 32 + nf * 8 + lc;
            const float* cc = acc[mf*4+nf];
            if (EPI == 0) {
                const int which = col >> 10;
                const int c = col & (DIM - 1);
                __half* Op = (which == 0) ? O0 : (which == 1) ? O1 : O2;
                *(__half2*)(Op + (size_t)row * DIM + c)       = __floats2half2_rn(cc[0], cc[1]);
                *(__half2*)(Op + (size_t)(row + 8) * DIM + c) = __floats2half2_rn(cc[2], cc[3]);
            } else if (EPI == 1) {
                float2 bb = *(const float2*)(bias + col);
                float v0 = fmaxf(cc[0] + bb.x, 0.f), v1 = fmaxf(cc[1] + bb.y, 0.f);
                float v2 = fmaxf(cc[2] + bb.x, 0.f), v3 = fmaxf(cc[3] + bb.y, 0.f);
                *(__half2*)(O0 + (size_t)row * N + col)       = __floats2half2_rn(v0, v1);
                *(__half2*)(O0 + (size_t)(row + 8) * N + col) = __floats2half2_rn(v2, v3);
            } else {
                float2 bb = *(const float2*)(bias + col);
                float2 r0 = *(const float2*)(res + (size_t)row * N + col);
                float2 r1 = *(const float2*)(res + (size_t)(row + 8) * N + col);
                float2 v0 = make_float2(cc[0] + bb.x + r0.x, cc[1] + bb.y + r0.y);
                float2 v1 = make_float2(cc[2] + bb.x + r1.x, cc[3] + bb.y + r1.y);
                *(float2*)(Cf + (size_t)row * N + col)       = v0;
                *(float2*)(Cf + (size_t)(row + 8) * N + col) = v1;
            }
        }
    }
}

// ==================== mma flash attention (fp16, 1-pass S) ===================
// grid (SEQ/128, HEADS, BATCH), 256 threads (8 warps, warp w owns rows w*16..+15).
#define QSTR 72
#define SM_Q  0
#define SM_K  (128*QSTR*2)                    // 18432 ; 2 bufs x 9216
#define SM_V  (SM_K + 2*9216)                 // 36864 ; 2 bufs x 9216
#define ATTN_SMEM_BYTES (SM_V + 2*9216)       // 55296
#define CEXP 0.1803368801111f                 // log2(e)/8

__global__ __launch_bounds__(256)
void attn_mma_kernel(const __half* __restrict__ Q_, const __half* __restrict__ K_,
                     const __half* __restrict__ V_, __half* __restrict__ O)
{
    extern __shared__ __align__(16) char smraw[];
    const uint32_t sb = smem_to_u32(smraw);
    const int tid = threadIdx.x, lane = tid & 31, w = tid >> 5;
    const int h = blockIdx.y, bz = blockIdx.z;
    const int rowbase = bz * SEQ + blockIdx.x * 128;
    const size_t gQrow0 = (size_t)rowbase * DIM + h * HSZ;
    const size_t gKbase = (size_t)bz * SEQ * DIM + h * HSZ;

    // ---- stage Q ----
    {
        int r = tid >> 1, cc = (tid & 1) * 4;
        const char* gq = (const char*)(Q_ + gQrow0 + (size_t)r * DIM);
        uint32_t sq = sb + SM_Q + (uint32_t)(r * QSTR) * 2;
        #pragma unroll
        for (int i = 0; i < 4; i++)
            cp16(sq + (cc + i) * 16, gq + (cc + i) * 16);
    }
    auto stageKV = [&](int it, int buf) {
        int r = tid >> 2, c0 = (tid & 3) * 32;
        size_t grow = gKbase + (size_t)(it * 64 + r) * DIM;
        uint32_t kk = sb + SM_K + (uint32_t)buf * 9216 + (uint32_t)(r * QSTR) * 2;
        uint32_t vv = sb + SM_V + (uint32_t)buf * 9216 + (uint32_t)(r * QSTR) * 2;
        cp16(kk + c0,      (const char*)(K_ + grow) + c0);
        cp16(kk + c0 + 16, (const char*)(K_ + grow) + c0 + 16);
        cp16(vv + c0,      (const char*)(V_ + grow) + c0);
        cp16(vv + c0 + 16, (const char*)(V_ + grow) + c0 + 16);
    };
    stageKV(0, 0);
    cp_commit();

    // A-operand lane pattern (Q, and V-trans)
    const int frow = (lane & 7) + ((lane >> 3) & 1) * 8;
    const int fcol = (lane >> 4) * 8;
    // B-operand lane pattern (K, non-trans)
    const int kbrow = (lane & 7) + (lane >> 4) * 8;
    const int kbcol = ((lane >> 3) & 1) * 8;

    uint32_t qf[4][4];
    float acc[8][4], lacc[4];
    #pragma unroll
    for (int i = 0; i < 8; i++)
        #pragma unroll
        for (int j = 0; j < 4; j++) acc[i][j] = 0.f;
    #pragma unroll
    for (int j = 0; j < 4; j++) lacc[j] = 0.f;
    float mr0 = -1e30f, mr1 = -1e30f;
    const uint32_t ones2[2] = {0x3C003C00u, 0x3C003C00u};

    const int NT = SEQ / 64;
    for (int it = 0; it < NT; it++) {
        const int buf = it & 1;
        if (it + 1 < NT) { stageKV(it + 1, buf ^ 1); cp_commit(); cp_wait1(); }
        else             { cp_wait0(); }
        __syncthreads();

        if (it == 0) {
            #pragma unroll
            for (int ks = 0; ks < 4; ks++) {
                uint32_t off = (uint32_t)((w * 16 + frow) * QSTR + ks * 16 + fcol) * 2;
                ldsm4(sb + SM_Q + off, qf[ks]);
            }
        }

        // ---- S = Q K^T (single-pass fp16) ----
        float sC[8][4];
        #pragma unroll
        for (int i = 0; i < 8; i++)
            #pragma unroll
            for (int j = 0; j < 4; j++) sC[i][j] = 0.f;

        const uint32_t kbase = sb + SM_K + (uint32_t)buf * 9216;
        #pragma unroll
        for (int ks = 0; ks < 4; ks++) {
            uint32_t kb[8][2];
            #pragma unroll
            for (int nfp = 0; nfp < 4; nfp++) {
                uint32_t off = (uint32_t)((nfp * 16 + kbrow) * QSTR + ks * 16 + kbcol) * 2;
                uint32_t r[4];
                ldsm4(kbase + off, r);
                kb[2*nfp][0] = r[0]; kb[2*nfp][1] = r[1];
                kb[2*nfp+1][0] = r[2]; kb[2*nfp+1][1] = r[3];
            }
            #pragma unroll
            for (int nt = 0; nt < 8; nt++) mma16816h(sC[nt], qf[ks], kb[nt]);
        }

        // ---- online softmax (raw-score units, scale folded into CEXP) ----
        float m0 = -1e30f, m1 = -1e30f;
        #pragma unroll
        for (int nt = 0; nt < 8; nt++) {
            m0 = fmaxf(m0, fmaxf(sC[nt][0], sC[nt][1]));
            m1 = fmaxf(m1, fmaxf(sC[nt][2], sC[nt][3]));
        }
        m0 = fmaxf(m0, __shfl_xor_sync(0xffffffffu, m0, 1));
        m0 = fmaxf(m0, __shfl_xor_sync(0xffffffffu, m0, 2));
        m1 = fmaxf(m1, __shfl_xor_sync(0xffffffffu, m1, 1));
        m1 = fmaxf(m1, __shfl_xor_sync(0xffffffffu, m1, 2));
        const float mn0 = fmaxf(mr0, m0), mn1 = fmaxf(mr1, m1);
        const float al0 = ex2f((mr0 - mn0) * CEXP);
        const float al1 = ex2f((mr1 - mn1) * CEXP);
        mr0 = mn0; mr1 = mn1;
        if (__any_sync(0xffffffffu, (al0 < 1.f) || (al1 < 1.f))) {
            #pragma unroll
            for (int nt = 0; nt < 8; nt++) {
                acc[nt][0] *= al0; acc[nt][1] *= al0;
                acc[nt][2] *= al1; acc[nt][3] *= al1;
            }
            lacc[0] *= al0; lacc[1] *= al0; lacc[2] *= al1; lacc[3] *= al1;
        }

        uint32_t pf[8][2];
        #pragma unroll
        for (int nt = 0; nt < 8; nt++) {
            pf[nt][0] = packex2((sC[nt][1] - mn0) * CEXP, (sC[nt][0] - mn0) * CEXP);
            pf[nt][1] = packex2((sC[nt][3] - mn1) * CEXP, (sC[nt][2] - mn1) * CEXP);
        }

        // ---- O += P V ; l += P·1 ----
        const uint32_t vbase = sb + SM_V + (uint32_t)buf * 9216;
        #pragma unroll
        for (int kt = 0; kt < 4; kt++) {
            uint32_t a[4] = {pf[2*kt][0], pf[2*kt][1], pf[2*kt+1][0], pf[2*kt+1][1]};
            #pragma unroll
            for (int nv = 0; nv < 4; nv++) {
                uint32_t off = (uint32_t)((kt * 16 + frow) * QSTR + nv * 16 + fcol) * 2;
                uint32_t r[4];
                ldsm4t(vbase + off, r);
                mma16816h(acc[2*nv],     a, r);
                mma16816h(acc[2*nv + 1], a, r + 2);
            }
            mma16816h(lacc, a, ones2);
        }
        __syncthreads();
    }

    // ---- normalize + store fp16 ----
    const float il0 = 1.f / lacc[0];
    const float il1 = 1.f / lacc[2];
    const int r0 = rowbase + w * 16 + (lane >> 2);
    const int cb = h * HSZ + (lane & 3) * 2;
    #pragma unroll
    for (int nt = 0; nt < 8; nt++) {
        const int col = cb + nt * 8;
        *(__half2*)(O + (size_t)r0 * DIM + col) =
            __floats2half2_rn(acc[nt][0] * il0, acc[nt][1] * il0);
        *(__half2*)(O + (size_t)(r0 + 8) * DIM + col) =
            __floats2half2_rn(acc[nt][2] * il1, acc[nt][3] * il1);
    }
}

// ============================ launch =========================================
extern "C" void kernel_launch(void* const* d_in, const int* in_sizes, int n_in,
                              void* d_out, int out_size)
{
    const float* x     = (const float*)d_in[0];
    const float* Wq    = (const float*)d_in[1];
    const float* Wk    = (const float*)d_in[2];
    const float* Wv    = (const float*)d_in[3];
    const float* Wo    = (const float*)d_in[4];
    const float* bo    = (const float*)d_in[5];
    const float* W1    = (const float*)d_in[6];
    const float* b1    = (const float*)d_in[7];
    const float* W2    = (const float*)d_in[8];
    const float* b2    = (const float*)d_in[9];
    const float* ln1_g = (const float*)d_in[10];
    const float* ln1_b = (const float*)d_in[11];
    const float* ln2_g = (const float*)d_in[12];
    const float* ln2_b = (const float*)d_in[13];
    float* out = (float*)d_out;

    float *px1;
    __half *ph, *pq, *pk, *pv, *patt, *pff;
    __half *pwqkv, *pwo, *pw1, *pw2;
    cudaGetSymbolAddress((void**)&px1, g_x1);
    cudaGetSymbolAddress((void**)&ph,  g_h);
    cudaGetSymbolAddress((void**)&pq,  g_q);
    cudaGetSymbolAddress((void**)&pk,  g_k);
    cudaGetSymbolAddress((void**)&pv,  g_v);
    cudaGetSymbolAddress((void**)&patt, g_att);
    cudaGetSymbolAddress((void**)&pff, g_ff);
    cudaGetSymbolAddress((void**)&pwqkv, g_wqkv);
    cudaGetSymbolAddress((void**)&pwo, g_wo);
    cudaGetSymbolAddress((void**)&pw1, g_w1);
    cudaGetSymbolAddress((void**)&pw2, g_w2);

    cudaFuncSetAttribute(attn_mma_kernel, cudaFuncAttributeMaxDynamicSharedMemorySize,
                         ATTN_SMEM_BYTES);
    cudaFuncSetAttribute(mma_gemm<0>, cudaFuncAttributeMaxDynamicSharedMemorySize,
                         GEMM_SMEM_BYTES);
    cudaFuncSetAttribute(mma_gemm<1>, cudaFuncAttributeMaxDynamicSharedMemorySize,
                         GEMM_SMEM_BYTES);
    cudaFuncSetAttribute(mma_gemm<2>, cudaFuncAttributeMaxDynamicSharedMemorySize,
                         GEMM_SMEM_BYTES);

    // 0) weight transpose + fp16 convert
    wconv_qkv_kernel<<<dim3(DIM/32, DIM/32, 3), 256>>>(Wq, Wk, Wv, pwqkv);
    wconv_kernel<0><<<dim3(DIM/32, DIM/32), 256>>>(Wo, pwo, DIM, DIM);
    wconv_kernel<0><<<dim3(DIM/32, FFDIM/32), 256>>>(W1, pw1, FFDIM, DIM);
    wconv_kernel<0><<<dim3(FFDIM/32, DIM/32), 256>>>(W2, pw2, DIM, FFDIM);

    // 1) h = LN1(x) -> fp16
    ln_kernel<<<ROWS, 256>>>(x, ln1_g, ln1_b, ph);

    // 2) fused QKV projection -> fp16
    dim3 gQKV(NQKV / 128, ROWS / 128);           // (24, 32)
    mma_gemm<0><<<gQKV, 256, GEMM_SMEM_BYTES>>>(ph, pwqkv, nullptr, nullptr,
                                                nullptr, pq, pk, pv, ROWS, NQKV, DIM);

    // 3) attention (fp16 tensor-core flash) -> fp16
    dim3 gAttn(SEQ / 128, HEADS, BATCH);
    attn_mma_kernel<<<gAttn, 256, ATTN_SMEM_BYTES>>>(pq, pk, pv, patt);

    // 4) x1 = x + attn @ Wo + bo (fp32)
    dim3 gP(DIM / 128, ROWS / 128);              // (8, 32)
    mma_gemm<2><<<gP, 256, GEMM_SMEM_BYTES>>>(patt, pwo, bo, x,
                                              px1, nullptr, nullptr, nullptr, ROWS, DIM, DIM);

    // 5) h2 = LN2(x1) -> fp16
    ln_kernel<<<ROWS, 256>>>(px1, ln2_g, ln2_b, ph);

    // 6) ff = relu(h2 @ W1 + b1) -> fp16
    dim3 gF(FFDIM / 128, ROWS / 128);            // (32, 32)
    mma_gemm<1><<<gF, 256, GEMM_SMEM_BYTES>>>(ph, pw1, b1, nullptr,
                                              nullptr, pff, nullptr, nullptr, ROWS, FFDIM, DIM);

    // 7) out = x1 + ff @ W2 + b2 (fp32)
    mma_gemm<2><<<gP, 256, GEMM_SMEM_BYTES>>>(pff, pw2, b2, px1,
                                              out, nullptr, nullptr, nullptr, ROWS, DIM, FFDIM);
}